// round 7
// baseline (speedup 1.0000x reference)
#include <cuda_runtime.h>
#include <cstdint>

#define T_STEPS 1000
#define BATCH   256
#define NIN     128
#define NHID    512
#define NOUT    128

#define NBLK 128
#define NTHR 512
#define CLUSTER 8
#define BT 16      // batch rows per CTA (= per cluster)
#define HT 64      // hidden cols per CTA
#define KTOT 640   // 512 recurrent + 128 input

#define WST 68     // wu float-stride per k row (64 + 4 pad)
#define SST 20     // ss float-stride per k row (16 + 4 pad)

#define OFF_WU 0
#define OFF_SS (KTOT*WST)                 // 43520 floats
#define SMEM_FLOATS (OFF_SS + KTOT*SST)   // 56320 floats
#define SMEM_BYTES (SMEM_FLOATS*4)        // 225280 B

typedef unsigned long long u64;

__device__ __forceinline__ void ffma2(u64& d, u64 a, u64 b) {
  asm("fma.rn.f32x2 %0, %1, %2, %0;" : "+l"(d) : "l"(a), "l"(b));
}
__device__ __forceinline__ u64 add2(u64 a, u64 b) {
  u64 r; asm("add.rn.f32x2 %0, %1, %2;" : "=l"(r) : "l"(a), "l"(b)); return r;
}
__device__ __forceinline__ u64 bcast2(float s) {
  u64 r; asm("mov.b64 %0, {%1, %1};" : "=l"(r) : "f"(s)); return r;
}
__device__ __forceinline__ u64 pack2(float lo, float hi) {
  u64 r; asm("mov.b64 %0, {%1, %2};" : "=l"(r) : "f"(lo), "f"(hi)); return r;
}
__device__ __forceinline__ float2 unpack2(u64 p) {
  float2 f; asm("mov.b64 {%0, %1}, %2;" : "=f"(f.x), "=f"(f.y) : "l"(p)); return f;
}

#define CL_ARRIVE() asm volatile("barrier.cluster.arrive.aligned;" ::: "memory")
#define CL_WAIT()   asm volatile("barrier.cluster.wait.aligned;"   ::: "memory")

__global__ void __launch_bounds__(NTHR, 1) __cluster_dims__(CLUSTER, 1, 1)
bnn_kernel(const float* __restrict__ x,     // [T, B, NIN]
           const float* __restrict__ W_in,  // [NHID, NIN]
           const float* __restrict__ b_in,  // [NHID]
           const float* __restrict__ W_rec, // [NHID, NHID]
           const float* __restrict__ W_out, // [NOUT, NHID]
           const float* __restrict__ b_out, // [NOUT]
           float* __restrict__ out)         // [T, B, NOUT]
{
  extern __shared__ float sm[];
  float* wu = sm + OFF_WU;   // [k=640][68]: wu[k][hl] = W[h0+hl][k] (rec+in unified)
  float* ss = sm + OFF_SS;   // [k=640][20]: s (rows 0-511) + x (rows 512-639), k-major

  const int tid = threadIdx.x;
  const int blk = blockIdx.x;
  const int btile = blk >> 3;           // 16 b-tiles (one cluster each)
  const int htile = blk & 7;            // 8  h-tiles = cluster rank
  const int b0 = btile * BT;
  const int h0 = htile * HT;

  // ---- prologue: weights into SMEM k-major ----
  for (int i = tid; i < NHID*HT; i += NTHR) {
    int hl = i >> 9, k = i & 511;
    wu[k*WST + hl] = W_rec[(size_t)(h0 + hl)*NHID + k];
  }
  for (int i = tid; i < NIN*HT; i += NTHR) {
    int hl = i >> 7, k = i & 127;
    wu[(NHID + k)*WST + hl] = W_in[(size_t)(h0 + hl)*NIN + k];
  }
  // zero s region; stage x[0]
  for (int i = tid; i < NHID*(SST/4); i += NTHR)
    ((float4*)ss)[i] = make_float4(0.f, 0.f, 0.f, 0.f);
  __syncthreads();
  #pragma unroll
  for (int j = 0; j < 4; ++j) {
    int g = j*NTHR + tid;
    int c = g & 127, bl = g >> 7;
    ss[(NHID + c)*SST + bl] = __ldg(x + (size_t)(b0 + bl)*NIN + c);
  }
  __syncthreads();

  // ---- mapping: warp = bh(1)|ho(3); lane = ksl (32-way k-split) ----
  const int warp = tid >> 5;
  const int lane = tid & 31;
  const int bh = warp >> 3;             // 0/1: b-half (8 b)
  const int ho = warp & 7;              // 0..7: h-oct (8 h)
  const int ksl = lane;                 // k = ksl + 32r

  const float4*     sp4 = (const float4*)ss + ksl*(SST/4) + bh*2;
  const ulonglong2* wp2 = (const ulonglong2*)wu + ksl*(WST/4) + ho*2;

  // update ownership (post reduce-scatter): b = b0+bh*8+(lane>>2), h-pair at ho*8+(lane&3)*2
  const int ubl = bh*8 + (lane >> 2);            // local b (0..15)
  const int uh  = h0 + ho*8 + (lane & 3)*2;      // global h (row in every rank's ss)
  const float2 bin = *(const float2*)(b_in + uh);

  // precompute DSMEM peer addresses for the publish (same offset in all ranks)
  unsigned peer[CLUSTER];
  {
    unsigned loc;
    asm("{ .reg .u64 t; cvta.to.shared.u64 t, %1; cvt.u32.u64 %0, t; }"
        : "=r"(loc) : "l"(ss + uh*SST + ubl));
    #pragma unroll
    for (int r = 0; r < CLUSTER; ++r)
      asm("mapa.shared::cluster.u32 %0, %1, %2;" : "=r"(peer[r]) : "r"(loc), "r"(r));
  }

  // readout: warp covers o_e = htile*16+ho*2, o_o = +1; writer lanes (lane&3)==0
  const float* wo0 = W_out + (size_t)(htile*16 + ho*2) * NHID + ksl;
  const float* wo1 = wo0 + NHID;
  const int widx = lane >> 2;                   // 0..7 = bp*2+op
  const int wb   = b0 + bh*8 + (widx >> 1)*2;   // output b (pair start)
  const int wo_  = htile*16 + ho*2 + (widx & 1);
  const float bo = __ldg(b_out + wo_);

  float2 v  = make_float2(0.f, 0.f);
  float2 a0 = make_float2(0.f, 0.f);
  float2 a1 = make_float2(0.f, 0.f);
  float2 sp = make_float2(0.f, 0.f);

  for (int t = 0; t <= T_STEPS; ++t) {
    // ---- GEMM over ss (= s[t-1], x[t]) + fused readout partials (out[t-1]) ----
    u64 acc[32];                         // idx = bl*4 + hp  (bl 0..7, hp 0..3)
    #pragma unroll
    for (int i = 0; i < 32; ++i) acc[i] = 0;
    u64 racc[8] = {0,0,0,0,0,0,0,0};     // idx = bp*2 + op

    #pragma unroll
    for (int r = 0; r < 20; ++r) {
      float4     sa = sp4[r*160];        // b0..b3 of this k
      float4     sb = sp4[r*160 + 1];    // b4..b7
      ulonglong2 wA = wp2[r*544];        // h-pairs 0,1
      ulonglong2 wB = wp2[r*544 + 1];    // h-pairs 2,3
      u64 s0 = bcast2(sa.x), s1 = bcast2(sa.y), s2 = bcast2(sa.z), s3 = bcast2(sa.w);
      u64 s4 = bcast2(sb.x), s5 = bcast2(sb.y), s6 = bcast2(sb.z), s7 = bcast2(sb.w);
      ffma2(acc[ 0], s0, wA.x); ffma2(acc[ 1], s0, wA.y); ffma2(acc[ 2], s0, wB.x); ffma2(acc[ 3], s0, wB.y);
      ffma2(acc[ 4], s1, wA.x); ffma2(acc[ 5], s1, wA.y); ffma2(acc[ 6], s1, wB.x); ffma2(acc[ 7], s1, wB.y);
      ffma2(acc[ 8], s2, wA.x); ffma2(acc[ 9], s2, wA.y); ffma2(acc[10], s2, wB.x); ffma2(acc[11], s2, wB.y);
      ffma2(acc[12], s3, wA.x); ffma2(acc[13], s3, wA.y); ffma2(acc[14], s3, wB.x); ffma2(acc[15], s3, wB.y);
      ffma2(acc[16], s4, wA.x); ffma2(acc[17], s4, wA.y); ffma2(acc[18], s4, wB.x); ffma2(acc[19], s4, wB.y);
      ffma2(acc[20], s5, wA.x); ffma2(acc[21], s5, wA.y); ffma2(acc[22], s5, wB.x); ffma2(acc[23], s5, wB.y);
      ffma2(acc[24], s6, wA.x); ffma2(acc[25], s6, wA.y); ffma2(acc[26], s6, wB.x); ffma2(acc[27], s6, wB.y);
      ffma2(acc[28], s7, wA.x); ffma2(acc[29], s7, wA.y); ffma2(acc[30], s7, wB.x); ffma2(acc[31], s7, wB.y);
      if (r < 16) {                      // s-region only (k < 512)
        u64 w0b = bcast2(__ldcg(wo0 + 32*r));
        u64 w1b = bcast2(__ldcg(wo1 + 32*r));
        u64 p0 = pack2(sa.x, sa.y), p1 = pack2(sa.z, sa.w);
        u64 p2 = pack2(sb.x, sb.y), p3 = pack2(sb.z, sb.w);
        ffma2(racc[0], p0, w0b); ffma2(racc[1], p0, w1b);
        ffma2(racc[2], p1, w0b); ffma2(racc[3], p1, w1b);
        ffma2(racc[4], p2, w0b); ffma2(racc[5], p2, w1b);
        ffma2(racc[6], p3, w0b); ffma2(racc[7], p3, w1b);
      }
    }

    // all smem reads of this step are done (data-dependencies retired below) ->
    // signal cluster early; overlap reductions/update with peers finishing.
    const bool last = (t == T_STEPS);
    if (!last) CL_ARRIVE();

    // ---- in-warp reduce-scatter of acc (lane ends with full sum of acc[lane]) ----
    #pragma unroll
    for (int m = 16; m >= 1; m >>= 1) {
      bool hi = (lane & m) != 0;
      #pragma unroll
      for (int j = 0; j < m; ++j) {
        u64 snd = hi ? acc[j] : acc[m + j];
        u64 rcv = __shfl_xor_sync(0xffffffffu, snd, m);
        acc[j] = add2(hi ? acc[m + j] : acc[j], rcv);
      }
    }
    // acc[0] = y-partial-sum for (b = b0+ubl, h-pair = uh)

    // ---- readout reduce: scatter over lane bits 4..2, then sum bits 1..0 ----
    #pragma unroll
    for (int m = 16; m >= 4; m >>= 1) {
      bool hi = (lane & m) != 0;
      int half = m >> 2;
      #pragma unroll
      for (int j = 0; j < 4; ++j) {
        if (j < half) {
          u64 snd = hi ? racc[j] : racc[half + j];
          u64 rcv = __shfl_xor_sync(0xffffffffu, snd, m);
          racc[j] = add2(hi ? racc[half + j] : racc[j], rcv);
        }
      }
    }
    racc[0] = add2(racc[0], __shfl_xor_sync(0xffffffffu, racc[0], 2));
    racc[0] = add2(racc[0], __shfl_xor_sync(0xffffffffu, racc[0], 1));
    if (t >= 1 && (lane & 3) == 0) {
      float2 rv = unpack2(racc[0]);
      float* op = out + (size_t)(t - 1)*BATCH*NOUT + (size_t)wb*NOUT + wo_;
      op[0]    = rv.x + bo;
      op[NOUT] = rv.y + bo;
    }

    if (!last) {
      // ---- GLIFR update for (b0+ubl, uh..uh+1) ----
      float2 yy = unpack2(acc[0]);
      #define UPD(i) { \
        float y  = 0.5f*(yy.i + bin.i); \
        a0.i = fmaf(a0.i,  0.85f, -0.05f*sp.i); \
        a1.i = fmaf(a1.i, -0.5f,  -0.05f*sp.i); \
        float it = y + a0.i + a1.i + 700.0f; \
        v.i  = v.i*0.99f*(1.0f - 0.05f*sp.i) + 0.00101953125f*it; \
        sp.i = 20.0f / (1.0f + __expf(-v.i*0.02f)); }
      UPD(x); UPD(y);
      #undef UPD

      CL_WAIT();   // all ranks finished reading ss -> safe to overwrite s-region

      // ---- publish s[t] into ALL cluster ranks' ss via DSMEM ----
      #pragma unroll
      for (int r = 0; r < CLUSTER; ++r) {
        asm volatile("st.shared::cluster.f32 [%0], %1;"
                     :: "r"(peer[r]), "f"(sp.x) : "memory");
        asm volatile("st.shared::cluster.f32 [%0], %1;"
                     :: "r"(peer[r] + 4*SST), "f"(sp.y) : "memory");
      }

      // ---- stage x[t+1] into own x-region (before arrive: ordered by wait) ----
      {
        int tn = (t + 1 < T_STEPS) ? t + 1 : (T_STEPS - 1);
        const float* xr = x + (size_t)tn*BATCH*NIN;
        #pragma unroll
        for (int j = 0; j < 4; ++j) {
          int g = j*NTHR + tid;
          int c = g & 127, bl = g >> 7;
          ss[(NHID + c)*SST + bl] = __ldg(xr + (size_t)(b0 + bl)*NIN + c);
        }
      }

      CL_ARRIVE();   // release: publishes + x staging visible
      CL_WAIT();     // acquire: everyone's s[t] landed in our ss
    }
  }
}

extern "C" void kernel_launch(void* const* d_in, const int* in_sizes, int n_in,
                              void* d_out, int out_size) {
  const float* x     = (const float*)d_in[0];
  const float* W_in  = (const float*)d_in[1];
  const float* b_in  = (const float*)d_in[2];
  const float* W_rec = (const float*)d_in[3];
  const float* W_out = (const float*)d_in[4];
  const float* b_out = (const float*)d_in[5];
  float* out = (float*)d_out;

  cudaFuncSetAttribute(bnn_kernel,
                       cudaFuncAttributeMaxDynamicSharedMemorySize, SMEM_BYTES);
  bnn_kernel<<<NBLK, NTHR, SMEM_BYTES>>>(x, W_in, b_in, W_rec, W_out, b_out, out);
}

// round 8
// speedup vs baseline: 1.3272x; 1.3272x over previous
#include <cuda_runtime.h>
#include <cstdint>

#define T_STEPS 1000
#define BATCH   256
#define NIN     128
#define NHID    512
#define NOUT    128

#define NBLK 128
#define NTHR 512
#define BT 16      // batch rows per CTA
#define HT 64      // hidden cols per CTA

#define WST 68     // wu float-stride per k row (64 + 4 pad)
#define SST 20     // ss float-stride per k row (16 + 4 pad)
#define OST 516    // wos float-stride per o row

#define OFF_WU 0
#define OFF_SS (NHID*WST)                  // 34816 floats
#define OFF_WO (OFF_SS + NHID*SST)         // 45056 floats
#define SMEM_FLOATS (OFF_WO + 16*OST)      // 53312 floats
#define SMEM_BYTES (SMEM_FLOATS*4)         // 213248 B

// precomputed input projection xp[t][b][h] = x[t]@W_in^T  (512 MB, device-static)
__device__ float g_xp[(size_t)T_STEPS*BATCH*NHID];
// L2-resident k-major s ring (2 slots), accessed only via .cg
__device__ float    g_s_ringT[2*NHID*BATCH];   // [slot][h][b]
__device__ unsigned g_cnt1[8];
__device__ unsigned g_cnt2 = 0;
__device__ unsigned g_gen  = 0;

typedef unsigned long long u64;

__device__ __forceinline__ void ffma2(u64& d, u64 a, u64 b) {
  asm("fma.rn.f32x2 %0, %1, %2, %0;" : "+l"(d) : "l"(a), "l"(b));
}
__device__ __forceinline__ u64 add2(u64 a, u64 b) {
  u64 r; asm("add.rn.f32x2 %0, %1, %2;" : "=l"(r) : "l"(a), "l"(b)); return r;
}
__device__ __forceinline__ u64 bcast2(float s) {
  u64 r; asm("mov.b64 %0, {%1, %1};" : "=l"(r) : "f"(s)); return r;
}
__device__ __forceinline__ u64 pack2(float lo, float hi) {
  u64 r; asm("mov.b64 %0, {%1, %2};" : "=l"(r) : "f"(lo), "f"(hi)); return r;
}
__device__ __forceinline__ float2 unpack2(u64 p) {
  float2 f; asm("mov.b64 {%0, %1}, %2;" : "=f"(f.x), "=f"(f.y) : "l"(p)); return f;
}

// tree grid barrier: 8 group counters -> root -> generation bump
__device__ __forceinline__ void grid_barrier(int blk) {
  __syncthreads();
  if (threadIdx.x == 0) {
    asm volatile("fence.acq_rel.gpu;" ::: "memory");
    unsigned my = *((volatile unsigned*)&g_gen);
    unsigned o1 = atomicAdd(&g_cnt1[blk & 7], 1u);
    if (o1 == 15u) {
      atomicExch(&g_cnt1[blk & 7], 0u);
      unsigned o2 = atomicAdd(&g_cnt2, 1u);
      if (o2 == 7u) {
        atomicExch(&g_cnt2, 0u);
        asm volatile("fence.acq_rel.gpu;" ::: "memory");
        atomicExch(&g_gen, my + 1u);
      }
    }
    while (*((volatile unsigned*)&g_gen) == my) { }
    asm volatile("fence.acq_rel.gpu;" ::: "memory");
  }
  __syncthreads();
}

// ---------------- pre-pass: xp = x @ W_in^T  (M=T*B, N=512, K=128) ----------
#define PXS 68     // xs stride (64 m + pad)
#define PWS 132    // ws stride (128 n + pad)
#define POFF_WS (128*PXS)                 // 8704 floats
#define PSMEM_FLOATS (POFF_WS + 128*PWS)  // 25600 floats
#define PSMEM_BYTES (PSMEM_FLOATS*4)      // 102400 B

__global__ void __launch_bounds__(256, 1)
xp_kernel(const float* __restrict__ x, const float* __restrict__ W_in) {
  extern __shared__ float psm[];
  float* xs = psm;             // [k=128][68]: xs[k][m]
  float* ws = psm + POFF_WS;   // [k=128][132]: ws[k][n]

  const int tid = threadIdx.x;
  const int m0 = blockIdx.x * 64;     // row tile (T*B rows)
  const int n0 = blockIdx.y * 128;    // h tile

  const float4* x4 = (const float4*)x;
  const float4* w4 = (const float4*)W_in;
  #pragma unroll
  for (int j = 0; j < 8; ++j) {       // x tile: 64 rows x 32 float4
    int g = j*256 + tid;
    int row = g >> 5, c4 = g & 31;
    float4 vv = __ldg(x4 + (size_t)(m0 + row)*32 + c4);
    xs[(c4*4 + 0)*PXS + row] = vv.x;
    xs[(c4*4 + 1)*PXS + row] = vv.y;
    xs[(c4*4 + 2)*PXS + row] = vv.z;
    xs[(c4*4 + 3)*PXS + row] = vv.w;
  }
  #pragma unroll
  for (int j = 0; j < 16; ++j) {      // W_in tile: 128 rows x 32 float4
    int g = j*256 + tid;
    int row = g >> 5, c4 = g & 31;
    float4 vv = __ldg(w4 + (size_t)(n0 + row)*32 + c4);
    ws[(c4*4 + 0)*PWS + row] = vv.x;
    ws[(c4*4 + 1)*PWS + row] = vv.y;
    ws[(c4*4 + 2)*PWS + row] = vv.z;
    ws[(c4*4 + 3)*PWS + row] = vv.w;
  }
  __syncthreads();

  const int tm = (tid >> 4) * 4;      // 0..60
  const int tn = (tid & 15) * 8;      // 0..120
  float acc[4][8];
  #pragma unroll
  for (int i = 0; i < 4; ++i)
    #pragma unroll
    for (int j = 0; j < 8; ++j) acc[i][j] = 0.f;

  #pragma unroll 4
  for (int k = 0; k < 128; ++k) {
    float4 a  = *(const float4*)(xs + k*PXS + tm);
    float4 b0 = *(const float4*)(ws + k*PWS + tn);
    float4 b1 = *(const float4*)(ws + k*PWS + tn + 4);
    float av[4] = {a.x, a.y, a.z, a.w};
    float bv[8] = {b0.x, b0.y, b0.z, b0.w, b1.x, b1.y, b1.z, b1.w};
    #pragma unroll
    for (int i = 0; i < 4; ++i)
      #pragma unroll
      for (int j = 0; j < 8; ++j)
        acc[i][j] = fmaf(av[i], bv[j], acc[i][j]);
  }

  float4* xp4 = (float4*)g_xp;
  #pragma unroll
  for (int i = 0; i < 4; ++i) {
    size_t rowb = (size_t)(m0 + tm + i)*(NHID/4) + (n0 + tn)/4;
    xp4[rowb]     = make_float4(acc[i][0], acc[i][1], acc[i][2], acc[i][3]);
    xp4[rowb + 1] = make_float4(acc[i][4], acc[i][5], acc[i][6], acc[i][7]);
  }
}

// ---------------- main persistent recurrent kernel --------------------------
__global__ void __launch_bounds__(NTHR, 1)
bnn_kernel(const float* __restrict__ x,     // [T, B, NIN] (unused here)
           const float* __restrict__ b_in,  // [NHID]
           const float* __restrict__ W_rec, // [NHID, NHID]
           const float* __restrict__ W_out, // [NOUT, NHID]
           const float* __restrict__ b_out, // [NOUT]
           float* __restrict__ out)         // [T, B, NOUT]
{
  extern __shared__ float sm[];
  float* wu  = sm + OFF_WU;  // [k=512][68]: wu[k][hl] = W_rec[h0+hl][k]
  float* ss  = sm + OFF_SS;  // [k=512][20]: s k-major
  float* wos = sm + OFF_WO;  // [o=16][516]: W_out rows htile*16..+15

  const int tid = threadIdx.x;
  const int blk = blockIdx.x;
  const int btile = blk >> 3;           // 16 b-tiles
  const int htile = blk & 7;            // 8  h-tiles
  const int b0 = btile * BT;
  const int h0 = htile * HT;

  // ---- prologue ----
  for (int i = tid; i < NHID*HT; i += NTHR) {
    int hl = i >> 9, k = i & 511;
    wu[k*WST + hl] = W_rec[(size_t)(h0 + hl)*NHID + k];
  }
  for (int i = tid; i < 16*NHID; i += NTHR) {
    int ol = i >> 9, k = i & 511;
    wos[ol*OST + k] = W_out[(size_t)(htile*16 + ol)*NHID + k];
  }
  for (int i = tid; i < NHID*(SST/4); i += NTHR)
    ((float4*)ss)[i] = make_float4(0.f, 0.f, 0.f, 0.f);
  __syncthreads();

  // ---- mapping: warp = bh(1)|ho(3); lane = ksl (32-way k-split) ----
  const int warp = tid >> 5;
  const int lane = tid & 31;
  const int bh = warp >> 3;             // 0/1: b-half (8 b)
  const int ho = warp & 7;              // 0..7: h-oct (8 h)
  const int ksl = lane;                 // k = ksl + 32r

  const float4*     sp4 = (const float4*)ss + ksl*(SST/4) + bh*2;
  const ulonglong2* wp2 = (const ulonglong2*)wu + ksl*(WST/4) + ho*2;
  const float* wos0 = wos + (ho*2)*OST + ksl;
  const float* wos1 = wos0 + OST;

  // update ownership: b = b0+ubl, h-pair at uh
  const int ubl = bh*8 + (lane >> 2);            // local b (0..15)
  const int uh  = h0 + ho*8 + (lane & 3)*2;      // global h
  const float2 bin = *(const float2*)(b_in + uh);

  // readout writer lanes
  const int widx = lane >> 2;                    // 0..7 = bp*2+op
  const int wb   = b0 + bh*8 + (widx >> 1)*2;
  const int wo_  = htile*16 + ho*2 + (widx & 1);
  const float bo = __ldg(b_out + wo_);

  float2 v  = make_float2(0.f, 0.f);
  float2 a0 = make_float2(0.f, 0.f);
  float2 a1 = make_float2(0.f, 0.f);
  float2 sp = make_float2(0.f, 0.f);

  for (int t = 0; t <= T_STEPS; ++t) {
    // prefetch this step's input-projection contribution (consumed at update)
    float2 xv = make_float2(0.f, 0.f);
    if (t < T_STEPS)
      xv = __ldcg((const float2*)(g_xp + (size_t)t*BATCH*NHID
                                  + (size_t)(b0 + ubl)*NHID + uh));

    // ---- GEMM over ss (= s[t-1]) + fused readout partials (out[t-1]) ----
    u64 acc[32];                        // idx = bl*4 + hp
    #pragma unroll
    for (int i = 0; i < 32; ++i) acc[i] = 0;
    u64 racc[8] = {0,0,0,0,0,0,0,0};    // idx = bp*2 + op

    #pragma unroll
    for (int r = 0; r < 16; ++r) {
      float4     sa = sp4[r*160];       // b0..b3 of this k
      float4     sb = sp4[r*160 + 1];   // b4..b7
      ulonglong2 wA = wp2[r*544];       // h-pairs 0,1
      ulonglong2 wB = wp2[r*544 + 1];   // h-pairs 2,3
      u64 s0 = bcast2(sa.x), s1 = bcast2(sa.y), s2 = bcast2(sa.z), s3 = bcast2(sa.w);
      u64 s4 = bcast2(sb.x), s5 = bcast2(sb.y), s6 = bcast2(sb.z), s7 = bcast2(sb.w);
      ffma2(acc[ 0], s0, wA.x); ffma2(acc[ 1], s0, wA.y); ffma2(acc[ 2], s0, wB.x); ffma2(acc[ 3], s0, wB.y);
      ffma2(acc[ 4], s1, wA.x); ffma2(acc[ 5], s1, wA.y); ffma2(acc[ 6], s1, wB.x); ffma2(acc[ 7], s1, wB.y);
      ffma2(acc[ 8], s2, wA.x); ffma2(acc[ 9], s2, wA.y); ffma2(acc[10], s2, wB.x); ffma2(acc[11], s2, wB.y);
      ffma2(acc[12], s3, wA.x); ffma2(acc[13], s3, wA.y); ffma2(acc[14], s3, wB.x); ffma2(acc[15], s3, wB.y);
      ffma2(acc[16], s4, wA.x); ffma2(acc[17], s4, wA.y); ffma2(acc[18], s4, wB.x); ffma2(acc[19], s4, wB.y);
      ffma2(acc[20], s5, wA.x); ffma2(acc[21], s5, wA.y); ffma2(acc[22], s5, wB.x); ffma2(acc[23], s5, wB.y);
      ffma2(acc[24], s6, wA.x); ffma2(acc[25], s6, wA.y); ffma2(acc[26], s6, wB.x); ffma2(acc[27], s6, wB.y);
      ffma2(acc[28], s7, wA.x); ffma2(acc[29], s7, wA.y); ffma2(acc[30], s7, wB.x); ffma2(acc[31], s7, wB.y);
      // readout partials from the same s registers
      u64 w0b = bcast2(wos0[32*r]);
      u64 w1b = bcast2(wos1[32*r]);
      u64 p0 = pack2(sa.x, sa.y), p1 = pack2(sa.z, sa.w);
      u64 p2 = pack2(sb.x, sb.y), p3 = pack2(sb.z, sb.w);
      ffma2(racc[0], p0, w0b); ffma2(racc[1], p0, w1b);
      ffma2(racc[2], p1, w0b); ffma2(racc[3], p1, w1b);
      ffma2(racc[4], p2, w0b); ffma2(racc[5], p2, w1b);
      ffma2(racc[6], p3, w0b); ffma2(racc[7], p3, w1b);
    }

    // ---- in-warp reduce-scatter of acc (lane ends with sum of acc[lane]) ----
    #pragma unroll
    for (int m = 16; m >= 1; m >>= 1) {
      bool hi = (lane & m) != 0;
      #pragma unroll
      for (int j = 0; j < m; ++j) {
        u64 snd = hi ? acc[j] : acc[m + j];
        u64 rcv = __shfl_xor_sync(0xffffffffu, snd, m);
        acc[j] = add2(hi ? acc[m + j] : acc[j], rcv);
      }
    }

    // ---- readout reduce: scatter over bits 4..2, then sum bits 1..0 ----
    #pragma unroll
    for (int m = 16; m >= 4; m >>= 1) {
      bool hi = (lane & m) != 0;
      int half = m >> 2;
      #pragma unroll
      for (int j = 0; j < 4; ++j) {
        if (j < half) {
          u64 snd = hi ? racc[j] : racc[half + j];
          u64 rcv = __shfl_xor_sync(0xffffffffu, snd, m);
          racc[j] = add2(hi ? racc[half + j] : racc[j], rcv);
        }
      }
    }
    racc[0] = add2(racc[0], __shfl_xor_sync(0xffffffffu, racc[0], 2));
    racc[0] = add2(racc[0], __shfl_xor_sync(0xffffffffu, racc[0], 1));
    if (t >= 1 && (lane & 3) == 0) {
      float2 rv = unpack2(racc[0]);
      float* op = out + (size_t)(t - 1)*BATCH*NOUT + (size_t)wb*NOUT + wo_;
      op[0]    = rv.x + bo;
      op[NOUT] = rv.y + bo;
    }

    if (t < T_STEPS) {
      // ---- GLIFR update for (b0+ubl, uh..uh+1) ----
      float2 yy = unpack2(acc[0]);
      #define UPD(i) { \
        float y  = 0.5f*(yy.i + xv.i + bin.i); \
        a0.i = fmaf(a0.i,  0.85f, -0.05f*sp.i); \
        a1.i = fmaf(a1.i, -0.5f,  -0.05f*sp.i); \
        float it = y + a0.i + a1.i + 700.0f; \
        v.i  = v.i*0.99f*(1.0f - 0.05f*sp.i) + 0.00101953125f*it; \
        sp.i = 20.0f / (1.0f + __expf(-v.i*0.02f)); }
      UPD(x); UPD(y);
      #undef UPD

      // publish s[t] to k-major L2 ring
      const int slot = t & 1;
      float* rT = g_s_ringT + (size_t)slot*NHID*BATCH;
      __stcg(rT + (size_t)uh*BATCH + b0 + ubl, sp.x);
      __stcg(rT + (size_t)(uh + 1)*BATCH + b0 + ubl, sp.y);

      grid_barrier(blk);

      // ---- restage: ss <- ringT ----
      {
        const float4* rT4 = (const float4*)(g_s_ringT + (size_t)slot*NHID*BATCH);
        #pragma unroll
        for (int j = 0; j < 4; ++j) {
          int g = j*NTHR + tid;
          int k = g & 511, bq = g >> 9;
          float4 vv = __ldcg(rT4 + (size_t)k*(BATCH/4) + (b0 >> 2) + bq);
          *(float4*)(ss + k*SST + bq*4) = vv;
        }
      }
      __syncthreads();
    }
  }
}

extern "C" void kernel_launch(void* const* d_in, const int* in_sizes, int n_in,
                              void* d_out, int out_size) {
  const float* x     = (const float*)d_in[0];
  const float* W_in  = (const float*)d_in[1];
  const float* b_in  = (const float*)d_in[2];
  const float* W_rec = (const float*)d_in[3];
  const float* W_out = (const float*)d_in[4];
  const float* b_out = (const float*)d_in[5];
  float* out = (float*)d_out;

  cudaFuncSetAttribute(xp_kernel,
                       cudaFuncAttributeMaxDynamicSharedMemorySize, PSMEM_BYTES);
  cudaFuncSetAttribute(bnn_kernel,
                       cudaFuncAttributeMaxDynamicSharedMemorySize, SMEM_BYTES);

  dim3 pg((T_STEPS*BATCH)/64, NHID/128);
  xp_kernel<<<pg, 256, PSMEM_BYTES>>>(x, W_in);
  bnn_kernel<<<NBLK, NTHR, SMEM_BYTES>>>(x, b_in, W_rec, W_out, b_out, out);
}

// round 9
// speedup vs baseline: 1.4502x; 1.0927x over previous
#include <cuda_runtime.h>
#include <cstdint>

#define T_STEPS 1000
#define BATCH   256
#define NIN     128
#define NHID    512
#define NOUT    128

#define NBLK 128
#define NTHR 512
#define BT 16      // batch rows per CTA
#define HT 64      // hidden cols per CTA

#define WST 68     // wu float-stride per k row (64 + 4 pad)
#define SST 20     // ss float-stride per k row (16 + 4 pad)
#define OST 516    // wos float-stride per o row

#define OFF_WU 0
#define OFF_SS (NHID*WST)                  // 34816 floats
#define OFF_WO (OFF_SS + NHID*SST)         // 45056 floats
#define SMEM_FLOATS (OFF_WO + 16*OST)      // 53312 floats
#define SMEM_BYTES (SMEM_FLOATS*4)         // 213248 B

// precomputed input projection xp[t][b][h] = x[t]@W_in^T  (512 MB, device-static)
__device__ float g_xp[(size_t)T_STEPS*BATCH*NHID];
// L2-resident k-major s ring (2 slots), accessed only via .cg
__device__ float    g_s_ringT[2*NHID*BATCH];   // [slot][h][b]
__device__ unsigned g_cnt1[8];
__device__ unsigned g_cnt2 = 0;
__device__ unsigned g_gen  = 0;

typedef unsigned long long u64;

__device__ __forceinline__ void ffma2(u64& d, u64 a, u64 b) {
  asm("fma.rn.f32x2 %0, %1, %2, %0;" : "+l"(d) : "l"(a), "l"(b));
}
__device__ __forceinline__ u64 add2(u64 a, u64 b) {
  u64 r; asm("add.rn.f32x2 %0, %1, %2;" : "=l"(r) : "l"(a), "l"(b)); return r;
}
__device__ __forceinline__ u64 bcast2(float s) {
  u64 r; asm("mov.b64 %0, {%1, %1};" : "=l"(r) : "f"(s)); return r;
}
__device__ __forceinline__ u64 pack2(float lo, float hi) {
  u64 r; asm("mov.b64 %0, {%1, %2};" : "=l"(r) : "f"(lo), "f"(hi)); return r;
}
__device__ __forceinline__ float2 unpack2(u64 p) {
  float2 f; asm("mov.b64 {%0, %1}, %2;" : "=f"(f.x), "=f"(f.y) : "l"(p)); return f;
}

// tree grid barrier: 8 group counters -> root -> generation bump
__device__ __forceinline__ void grid_barrier(int blk) {
  __syncthreads();
  if (threadIdx.x == 0) {
    asm volatile("fence.acq_rel.gpu;" ::: "memory");
    unsigned my = *((volatile unsigned*)&g_gen);
    unsigned o1 = atomicAdd(&g_cnt1[blk & 7], 1u);
    if (o1 == 15u) {
      atomicExch(&g_cnt1[blk & 7], 0u);
      unsigned o2 = atomicAdd(&g_cnt2, 1u);
      if (o2 == 7u) {
        atomicExch(&g_cnt2, 0u);
        asm volatile("fence.acq_rel.gpu;" ::: "memory");
        atomicExch(&g_gen, my + 1u);
      }
    }
    while (*((volatile unsigned*)&g_gen) == my) { }
    asm volatile("fence.acq_rel.gpu;" ::: "memory");
  }
  __syncthreads();
}

// ---------------- pre-pass v2: xp = x @ W_in^T  (M=T*B=256000, N=512, K=128) --
// 128m x 256n per block, 512 threads, 8x8 f32x2 per thread, XOR-swizzled tiles.
#define PM 128
#define PN 256
#define PMST 136
#define PNST 264
#define POFF_WS (NIN*PMST)                  // 17408 floats
#define PSMEM_FLOATS (POFF_WS + NIN*PNST)   // 51200 floats
#define PSMEM_BYTES (PSMEM_FLOATS*4)        // 204800 B

__global__ void __launch_bounds__(512, 1)
xp_kernel(const float* __restrict__ x, const float* __restrict__ W_in) {
  extern __shared__ float psm[];
  float* xs = psm;             // [k=128][136]: slot m' = m ^ xk
  float* ws = psm + POFF_WS;   // [k=128][264]: slot n' = n ^ xk

  const int tid = threadIdx.x;
  const int m0 = blockIdx.x * PM;
  const int n0 = blockIdx.y * PN;

  // load + transpose x tile [128m][128k] -> xs[k][m^xk]
  const float4* x4 = (const float4*)x;
  #pragma unroll
  for (int j = 0; j < 8; ++j) {
    int g = j*512 + tid;                 // 0..4095
    int row = g >> 5, c4 = g & 31;
    float4 vv = __ldg(x4 + (size_t)(m0 + row)*32 + c4);
    float va[4] = {vv.x, vv.y, vv.z, vv.w};
    #pragma unroll
    for (int i = 0; i < 4; ++i) {
      int k = 4*c4 + i;
      int xk = ((k >> 2) & 7) << 2;
      xs[k*PMST + (row ^ xk)] = va[i];
    }
  }
  // load + transpose W tile [256n][128k] -> ws[k][n^xk]
  const float4* w4 = (const float4*)W_in;
  #pragma unroll
  for (int j = 0; j < 16; ++j) {
    int g = j*512 + tid;                 // 0..8191
    int row = g >> 5, c4 = g & 31;
    float4 vv = __ldg(w4 + (size_t)(n0 + row)*32 + c4);
    float va[4] = {vv.x, vv.y, vv.z, vv.w};
    #pragma unroll
    for (int i = 0; i < 4; ++i) {
      int k = 4*c4 + i;
      int xk = ((k >> 2) & 7) << 2;
      ws[k*PNST + (row ^ xk)] = va[i];
    }
  }
  __syncthreads();

  const int tm = (tid & 15) * 8;         // 16 m-tiles
  const int tn = (tid >> 4) * 8;         // 32 n-tiles
  u64 acc[8][4];                         // [mi][n-pair]
  #pragma unroll
  for (int i = 0; i < 8; ++i)
    #pragma unroll
    for (int j = 0; j < 4; ++j) acc[i][j] = 0;

  #pragma unroll 8
  for (int k = 0; k < NIN; ++k) {
    int xk = ((k >> 2) & 7) << 2;
    const float* xr = xs + k*PMST;
    const float* wr = ws + k*PNST;
    float4 a0 = *(const float4*)(xr + (tm ^ xk));
    float4 a1 = *(const float4*)(xr + ((tm + 4) ^ xk));
    ulonglong2 b0 = *(const ulonglong2*)(wr + (tn ^ xk));
    ulonglong2 b1 = *(const ulonglong2*)(wr + ((tn + 4) ^ xk));
    float am[8] = {a0.x, a0.y, a0.z, a0.w, a1.x, a1.y, a1.z, a1.w};
    u64 bn[4] = {b0.x, b0.y, b1.x, b1.y};
    #pragma unroll
    for (int mi = 0; mi < 8; ++mi) {
      u64 ab = bcast2(am[mi]);
      ffma2(acc[mi][0], ab, bn[0]);
      ffma2(acc[mi][1], ab, bn[1]);
      ffma2(acc[mi][2], ab, bn[2]);
      ffma2(acc[mi][3], ab, bn[3]);
    }
  }

  float4* xp4 = (float4*)g_xp;
  #pragma unroll
  for (int mi = 0; mi < 8; ++mi) {
    float2 p0 = unpack2(acc[mi][0]), p1 = unpack2(acc[mi][1]);
    float2 p2 = unpack2(acc[mi][2]), p3 = unpack2(acc[mi][3]);
    size_t rb = (size_t)(m0 + tm + mi)*(NHID/4) + (size_t)(n0 + tn)/4;
    xp4[rb]     = make_float4(p0.x, p0.y, p1.x, p1.y);
    xp4[rb + 1] = make_float4(p2.x, p2.y, p3.x, p3.y);
  }
}

// ---------------- main persistent recurrent kernel --------------------------
__global__ void __launch_bounds__(NTHR, 1)
bnn_kernel(const float* __restrict__ b_in,  // [NHID]
           const float* __restrict__ W_rec, // [NHID, NHID]
           const float* __restrict__ W_out, // [NOUT, NHID]
           const float* __restrict__ b_out, // [NOUT]
           float* __restrict__ out)         // [T, B, NOUT]
{
  extern __shared__ float sm[];
  float* wu  = sm + OFF_WU;  // [k=512][68]: wu[k][hl] = W_rec[h0+hl][k]
  float* ss  = sm + OFF_SS;  // [k=512][20]: s k-major
  float* wos = sm + OFF_WO;  // [o=16][516]: W_out rows htile*16..+15

  const int tid = threadIdx.x;
  const int blk = blockIdx.x;
  const int btile = blk >> 3;           // 16 b-tiles
  const int htile = blk & 7;            // 8  h-tiles
  const int b0 = btile * BT;
  const int h0 = htile * HT;

  // ---- prologue ----
  for (int i = tid; i < NHID*HT; i += NTHR) {
    int hl = i >> 9, k = i & 511;
    wu[k*WST + hl] = W_rec[(size_t)(h0 + hl)*NHID + k];
  }
  for (int i = tid; i < 16*NHID; i += NTHR) {
    int ol = i >> 9, k = i & 511;
    wos[ol*OST + k] = W_out[(size_t)(htile*16 + ol)*NHID + k];
  }
  for (int i = tid; i < NHID*(SST/4); i += NTHR)
    ((float4*)ss)[i] = make_float4(0.f, 0.f, 0.f, 0.f);
  __syncthreads();

  // ---- mapping: warp = bh(1)|ho(3); lane = ksl (32-way k-split) ----
  const int warp = tid >> 5;
  const int lane = tid & 31;
  const int bh = warp >> 3;             // 0/1: b-half (8 b)
  const int ho = warp & 7;              // 0..7: h-oct (8 h)
  const int ksl = lane;                 // k = ksl + 32r

  const float4*     sp4 = (const float4*)ss + ksl*(SST/4) + bh*2;
  const ulonglong2* wp2 = (const ulonglong2*)wu + ksl*(WST/4) + ho*2;
  const float* wos0 = wos + (ho*2)*OST + ksl;
  const float* wos1 = wos0 + OST;

  // update ownership: b = b0+ubl, h-pair at uh
  const int ubl = bh*8 + (lane >> 2);            // local b (0..15)
  const int uh  = h0 + ho*8 + (lane & 3)*2;      // global h
  const float2 bin = *(const float2*)(b_in + uh);

  // readout writer lanes
  const int widx = lane >> 2;                    // 0..7 = bp*2+op
  const int wb   = b0 + bh*8 + (widx >> 1)*2;
  const int wo_  = htile*16 + ho*2 + (widx & 1);
  const float bo = __ldg(b_out + wo_);

  float2 v  = make_float2(0.f, 0.f);
  float2 a0 = make_float2(0.f, 0.f);
  float2 a1 = make_float2(0.f, 0.f);
  float2 sp = make_float2(0.f, 0.f);

  for (int t = 0; t <= T_STEPS; ++t) {
    // prefetch this step's input-projection contribution (consumed at update)
    float2 xv = make_float2(0.f, 0.f);
    if (t < T_STEPS)
      xv = __ldcg((const float2*)(g_xp + (size_t)t*BATCH*NHID
                                  + (size_t)(b0 + ubl)*NHID + uh));

    // ---- GEMM over ss (= s[t-1]) + fused readout partials (out[t-1]) ----
    u64 acc[32];                        // idx = bl*4 + hp
    #pragma unroll
    for (int i = 0; i < 32; ++i) acc[i] = 0;
    u64 racc[8] = {0,0,0,0,0,0,0,0};    // idx = bp*2 + op

    #pragma unroll
    for (int r = 0; r < 16; ++r) {
      float4     sa = sp4[r*160];       // b0..b3 of this k
      float4     sb = sp4[r*160 + 1];   // b4..b7
      ulonglong2 wA = wp2[r*544];       // h-pairs 0,1
      ulonglong2 wB = wp2[r*544 + 1];   // h-pairs 2,3
      u64 s0 = bcast2(sa.x), s1 = bcast2(sa.y), s2 = bcast2(sa.z), s3 = bcast2(sa.w);
      u64 s4 = bcast2(sb.x), s5 = bcast2(sb.y), s6 = bcast2(sb.z), s7 = bcast2(sb.w);
      ffma2(acc[ 0], s0, wA.x); ffma2(acc[ 1], s0, wA.y); ffma2(acc[ 2], s0, wB.x); ffma2(acc[ 3], s0, wB.y);
      ffma2(acc[ 4], s1, wA.x); ffma2(acc[ 5], s1, wA.y); ffma2(acc[ 6], s1, wB.x); ffma2(acc[ 7], s1, wB.y);
      ffma2(acc[ 8], s2, wA.x); ffma2(acc[ 9], s2, wA.y); ffma2(acc[10], s2, wB.x); ffma2(acc[11], s2, wB.y);
      ffma2(acc[12], s3, wA.x); ffma2(acc[13], s3, wA.y); ffma2(acc[14], s3, wB.x); ffma2(acc[15], s3, wB.y);
      ffma2(acc[16], s4, wA.x); ffma2(acc[17], s4, wA.y); ffma2(acc[18], s4, wB.x); ffma2(acc[19], s4, wB.y);
      ffma2(acc[20], s5, wA.x); ffma2(acc[21], s5, wA.y); ffma2(acc[22], s5, wB.x); ffma2(acc[23], s5, wB.y);
      ffma2(acc[24], s6, wA.x); ffma2(acc[25], s6, wA.y); ffma2(acc[26], s6, wB.x); ffma2(acc[27], s6, wB.y);
      ffma2(acc[28], s7, wA.x); ffma2(acc[29], s7, wA.y); ffma2(acc[30], s7, wB.x); ffma2(acc[31], s7, wB.y);
      // readout partials from the same s registers
      u64 w0b = bcast2(wos0[32*r]);
      u64 w1b = bcast2(wos1[32*r]);
      u64 p0 = pack2(sa.x, sa.y), p1 = pack2(sa.z, sa.w);
      u64 p2 = pack2(sb.x, sb.y), p3 = pack2(sb.z, sb.w);
      ffma2(racc[0], p0, w0b); ffma2(racc[1], p0, w1b);
      ffma2(racc[2], p1, w0b); ffma2(racc[3], p1, w1b);
      ffma2(racc[4], p2, w0b); ffma2(racc[5], p2, w1b);
      ffma2(racc[6], p3, w0b); ffma2(racc[7], p3, w1b);
    }

    float4 rv0, rv1, rv2, rv3;          // restage staging regs
    const int slot = t & 1;

    if (t < T_STEPS) {
      // ---- y reduce-scatter (lane ends with sum of acc[lane]) ----
      #pragma unroll
      for (int m = 16; m >= 1; m >>= 1) {
        bool hi = (lane & m) != 0;
        #pragma unroll
        for (int j = 0; j < m; ++j) {
          u64 snd = hi ? acc[j] : acc[m + j];
          u64 rcv = __shfl_xor_sync(0xffffffffu, snd, m);
          acc[j] = add2(hi ? acc[m + j] : acc[j], rcv);
        }
      }

      // ---- GLIFR update for (b0+ubl, uh..uh+1) ----
      float2 yy = unpack2(acc[0]);
      #define UPD(i) { \
        float y  = 0.5f*(yy.i + xv.i + bin.i); \
        a0.i = fmaf(a0.i,  0.85f, -0.05f*sp.i); \
        a1.i = fmaf(a1.i, -0.5f,  -0.05f*sp.i); \
        float it = y + a0.i + a1.i + 700.0f; \
        v.i  = v.i*0.99f*(1.0f - 0.05f*sp.i) + 0.00101953125f*it; \
        sp.i = 20.0f / (1.0f + __expf(-v.i*0.02f)); }
      UPD(x); UPD(y);
      #undef UPD

      // publish s[t] to k-major L2 ring
      float* rT = g_s_ringT + (size_t)slot*NHID*BATCH;
      __stcg(rT + (size_t)uh*BATCH + b0 + ubl, sp.x);
      __stcg(rT + (size_t)(uh + 1)*BATCH + b0 + ubl, sp.y);

      grid_barrier(blk);

      // issue restage loads NOW; their latency overlaps the readout reduce
      const float4* rT4 = (const float4*)(g_s_ringT + (size_t)slot*NHID*BATCH);
      {
        int g0 = tid;
        rv0 = __ldcg(rT4 + (size_t)(g0 & 511)*(BATCH/4) + (b0 >> 2) + (g0 >> 9));
        int g1 = NTHR + tid;
        rv1 = __ldcg(rT4 + (size_t)(g1 & 511)*(BATCH/4) + (b0 >> 2) + (g1 >> 9));
        int g2 = 2*NTHR + tid;
        rv2 = __ldcg(rT4 + (size_t)(g2 & 511)*(BATCH/4) + (b0 >> 2) + (g2 >> 9));
        int g3 = 3*NTHR + tid;
        rv3 = __ldcg(rT4 + (size_t)(g3 & 511)*(BATCH/4) + (b0 >> 2) + (g3 >> 9));
      }
    }

    // ---- readout reduce (overlaps restage loads): bits 4..2 scatter, 1..0 sum --
    #pragma unroll
    for (int m = 16; m >= 4; m >>= 1) {
      bool hi = (lane & m) != 0;
      int half = m >> 2;
      #pragma unroll
      for (int j = 0; j < 4; ++j) {
        if (j < half) {
          u64 snd = hi ? racc[j] : racc[half + j];
          u64 rcv = __shfl_xor_sync(0xffffffffu, snd, m);
          racc[j] = add2(hi ? racc[half + j] : racc[j], rcv);
        }
      }
    }
    racc[0] = add2(racc[0], __shfl_xor_sync(0xffffffffu, racc[0], 2));
    racc[0] = add2(racc[0], __shfl_xor_sync(0xffffffffu, racc[0], 1));
    if (t >= 1 && (lane & 3) == 0) {
      float2 rv = unpack2(racc[0]);
      float* op = out + (size_t)(t - 1)*BATCH*NOUT + (size_t)wb*NOUT + wo_;
      op[0]    = rv.x + bo;
      op[NOUT] = rv.y + bo;
    }

    if (t < T_STEPS) {
      // ---- commit restage to ss ----
      {
        int g0 = tid;
        *(float4*)(ss + (g0 & 511)*SST + (g0 >> 9)*4) = rv0;
        int g1 = NTHR + tid;
        *(float4*)(ss + (g1 & 511)*SST + (g1 >> 9)*4) = rv1;
        int g2 = 2*NTHR + tid;
        *(float4*)(ss + (g2 & 511)*SST + (g2 >> 9)*4) = rv2;
        int g3 = 3*NTHR + tid;
        *(float4*)(ss + (g3 & 511)*SST + (g3 >> 9)*4) = rv3;
      }
      __syncthreads();
    }
  }
}

extern "C" void kernel_launch(void* const* d_in, const int* in_sizes, int n_in,
                              void* d_out, int out_size) {
  const float* x     = (const float*)d_in[0];
  const float* W_in  = (const float*)d_in[1];
  const float* b_in  = (const float*)d_in[2];
  const float* W_rec = (const float*)d_in[3];
  const float* W_out = (const float*)d_in[4];
  const float* b_out = (const float*)d_in[5];
  float* out = (float*)d_out;

  cudaFuncSetAttribute(xp_kernel,
                       cudaFuncAttributeMaxDynamicSharedMemorySize, PSMEM_BYTES);
  cudaFuncSetAttribute(bnn_kernel,
                       cudaFuncAttributeMaxDynamicSharedMemorySize, SMEM_BYTES);

  dim3 pg((T_STEPS*BATCH)/PM, NHID/PN);   // (2000, 2)
  xp_kernel<<<pg, 512, PSMEM_BYTES>>>(x, W_in);
  bnn_kernel<<<NBLK, NTHR, SMEM_BYTES>>>(b_in, W_rec, W_out, b_out, out);
}

// round 11
// speedup vs baseline: 2.0547x; 1.4168x over previous
#include <cuda_runtime.h>
#include <cuda_bf16.h>
#include <cstdint>

#define T_STEPS 1000
#define BATCH   256
#define NIN     128
#define NHID    512
#define NOUT    128

#define NBLK 128
#define NTHR 384
#define BT 16      // batch rows per CTA
#define HT 64      // hidden cols per CTA

// smem: bf16 s tiles (hi, lo), row stride 520 bf16 = 1040 B (== 16 mod 128 ->
// ldmatrix 8-row fetches hit 8 distinct 16B groups: conflict-free)
#define SROW 520
#define SS_HI_B 0
#define SS_LO_B (16*SROW*2)            // 16640
#define OLO_B   (2*16*SROW*2)          // 33280: readout-lo exchange [16][18] f32
#define SMEM_BYTES (OLO_B + 16*18*4)   // 34432 B

// precomputed input projection xp[t][b][h] (512 MB, device-static)
__device__ float g_xp[(size_t)T_STEPS*BATCH*NHID];
// fp32 s ring (2 slots), b-major, L2-resident (.cg only)
__device__ float    g_ring[2][BATCH][NHID];
__device__ unsigned g_cnt1[8];
__device__ unsigned g_cnt2 = 0;
__device__ unsigned g_gen  = 0;

typedef unsigned long long u64;

__device__ __forceinline__ uint32_t smem_u32(const void* p) {
  uint32_t a;
  asm("{ .reg .u64 t; cvta.to.shared.u64 t, %1; cvt.u32.u64 %0, t; }"
      : "=r"(a) : "l"(p));
  return a;
}
__device__ __forceinline__ uint32_t pk2(float lo, float hi) {
  unsigned short a = __bfloat16_as_ushort(__float2bfloat16_rn(lo));
  unsigned short b = __bfloat16_as_ushort(__float2bfloat16_rn(hi));
  return (uint32_t)a | ((uint32_t)b << 16);
}
#define LDSM4(r0,r1,r2,r3,addr) \
  asm volatile("ldmatrix.sync.aligned.m8n8.x4.shared.b16 {%0,%1,%2,%3}, [%4];" \
    : "=r"(r0),"=r"(r1),"=r"(r2),"=r"(r3) : "r"(addr))
#define MMA16816(d, a0,a1,a2,a3, b0,b1) \
  asm volatile("mma.sync.aligned.m16n8k16.row.col.f32.bf16.bf16.f32 " \
    "{%0,%1,%2,%3}, {%4,%5,%6,%7}, {%8,%9}, {%0,%1,%2,%3};" \
    : "+f"((d)[0]),"+f"((d)[1]),"+f"((d)[2]),"+f"((d)[3]) \
    : "r"(a0),"r"(a1),"r"(a2),"r"(a3), "r"(b0),"r"(b1))

// tree grid barrier: 8 groups of 16 CTAs -> root
__device__ __forceinline__ void grid_barrier(int blk) {
  __syncthreads();
  if (threadIdx.x == 0) {
    asm volatile("fence.acq_rel.gpu;" ::: "memory");
    unsigned my = *((volatile unsigned*)&g_gen);
    unsigned o1 = atomicAdd(&g_cnt1[blk & 7], 1u);
    if (o1 == 15u) {
      atomicExch(&g_cnt1[blk & 7], 0u);
      unsigned o2 = atomicAdd(&g_cnt2, 1u);
      if (o2 == 7u) {
        atomicExch(&g_cnt2, 0u);
        asm volatile("fence.acq_rel.gpu;" ::: "memory");
        atomicExch(&g_gen, my + 1u);
      }
    }
    while (*((volatile unsigned*)&g_gen) == my) { }
    asm volatile("fence.acq_rel.gpu;" ::: "memory");
  }
  __syncthreads();
}

// ---------------- pre-pass: xp = x @ W_in^T (unchanged from R9) -------------
#define PM 128
#define PN 256
#define PMST 136
#define PNST 264
#define POFF_WS (NIN*PMST)
#define PSMEM_FLOATS (POFF_WS + NIN*PNST)
#define PSMEM_BYTES (PSMEM_FLOATS*4)

__device__ __forceinline__ void ffma2p(u64& d, u64 a, u64 b) {
  asm("fma.rn.f32x2 %0, %1, %2, %0;" : "+l"(d) : "l"(a), "l"(b));
}
__device__ __forceinline__ u64 bcast2p(float s) {
  u64 r; asm("mov.b64 %0, {%1, %1};" : "=l"(r) : "f"(s)); return r;
}
__device__ __forceinline__ float2 unpack2p(u64 p) {
  float2 f; asm("mov.b64 {%0, %1}, %2;" : "=f"(f.x), "=f"(f.y) : "l"(p)); return f;
}

__global__ void __launch_bounds__(512, 1)
xp_kernel(const float* __restrict__ x, const float* __restrict__ W_in) {
  extern __shared__ float psm[];
  float* xs = psm;
  float* ws = psm + POFF_WS;
  const int tid = threadIdx.x;
  const int m0 = blockIdx.x * PM;
  const int n0 = blockIdx.y * PN;

  const float4* x4 = (const float4*)x;
  #pragma unroll
  for (int j = 0; j < 8; ++j) {
    int g = j*512 + tid;
    int row = g >> 5, c4 = g & 31;
    float4 vv = __ldg(x4 + (size_t)(m0 + row)*32 + c4);
    float va[4] = {vv.x, vv.y, vv.z, vv.w};
    #pragma unroll
    for (int i = 0; i < 4; ++i) {
      int k = 4*c4 + i, xk = ((k >> 2) & 7) << 2;
      xs[k*PMST + (row ^ xk)] = va[i];
    }
  }
  const float4* w4 = (const float4*)W_in;
  #pragma unroll
  for (int j = 0; j < 16; ++j) {
    int g = j*512 + tid;
    int row = g >> 5, c4 = g & 31;
    float4 vv = __ldg(w4 + (size_t)(n0 + row)*32 + c4);
    float va[4] = {vv.x, vv.y, vv.z, vv.w};
    #pragma unroll
    for (int i = 0; i < 4; ++i) {
      int k = 4*c4 + i, xk = ((k >> 2) & 7) << 2;
      ws[k*PNST + (row ^ xk)] = va[i];
    }
  }
  __syncthreads();

  const int tm = (tid & 15) * 8;
  const int tn = (tid >> 4) * 8;
  u64 acc[8][4];
  #pragma unroll
  for (int i = 0; i < 8; ++i)
    #pragma unroll
    for (int j = 0; j < 4; ++j) acc[i][j] = 0;

  #pragma unroll 8
  for (int k = 0; k < NIN; ++k) {
    int xk = ((k >> 2) & 7) << 2;
    const float* xr = xs + k*PMST;
    const float* wr = ws + k*PNST;
    float4 a0 = *(const float4*)(xr + (tm ^ xk));
    float4 a1 = *(const float4*)(xr + ((tm + 4) ^ xk));
    ulonglong2 b0 = *(const ulonglong2*)(wr + (tn ^ xk));
    ulonglong2 b1 = *(const ulonglong2*)(wr + ((tn + 4) ^ xk));
    float am[8] = {a0.x, a0.y, a0.z, a0.w, a1.x, a1.y, a1.z, a1.w};
    u64 bn[4] = {b0.x, b0.y, b1.x, b1.y};
    #pragma unroll
    for (int mi = 0; mi < 8; ++mi) {
      u64 ab = bcast2p(am[mi]);
      ffma2p(acc[mi][0], ab, bn[0]);
      ffma2p(acc[mi][1], ab, bn[1]);
      ffma2p(acc[mi][2], ab, bn[2]);
      ffma2p(acc[mi][3], ab, bn[3]);
    }
  }
  float4* xp4 = (float4*)g_xp;
  #pragma unroll
  for (int mi = 0; mi < 8; ++mi) {
    float2 p0 = unpack2p(acc[mi][0]), p1 = unpack2p(acc[mi][1]);
    float2 p2 = unpack2p(acc[mi][2]), p3 = unpack2p(acc[mi][3]);
    size_t rb = (size_t)(m0 + tm + mi)*(NHID/4) + (size_t)(n0 + tn)/4;
    xp4[rb]     = make_float4(p0.x, p0.y, p1.x, p1.y);
    xp4[rb + 1] = make_float4(p2.x, p2.y, p3.x, p3.y);
  }
}

// ---------------- main persistent recurrent kernel (mma.sync HMMA) ----------
__global__ void __launch_bounds__(NTHR, 1)
bnn_kernel(const float* __restrict__ b_in,  // [NHID]
           const float* __restrict__ W_rec, // [NHID, NHID]
           const float* __restrict__ W_out, // [NOUT, NHID]
           const float* __restrict__ b_out, // [NOUT]
           float* __restrict__ out)         // [T, B, NOUT]
{
  extern __shared__ char smc[];
  const uint32_t smb = smem_u32(smc);
  float* olo = (float*)(smc + OLO_B);   // [16][18]

  const int tid = threadIdx.x;
  const int blk = blockIdx.x;
  const int btile = blk >> 3;           // 16 b-tiles
  const int htile = blk & 7;            // 8  h-tiles
  const int b0 = btile * BT;
  const int h0 = htile * HT;
  const int o0 = htile * 16;
  const int w  = tid >> 5;              // 0..11
  const int lane = tid & 31;

  // ---- B fragments in registers (loaded once); warp covers n-slice w*8 ----
  // n 0-63: W_rec h; n 64-79: W_out hi; n 80-95: W_out lo
  uint32_t bf0[32], bf1[32];
  {
    const int nn = w*8 + (lane >> 2);
    const float* wr;
    bool is_lo = false;
    if (nn < 64) wr = W_rec + (size_t)(h0 + nn)*NHID;
    else if (nn < 80) wr = W_out + (size_t)(o0 + nn - 64)*NHID;
    else { wr = W_out + (size_t)(o0 + nn - 80)*NHID; is_lo = true; }
    #pragma unroll
    for (int ks = 0; ks < 32; ++ks) {
      int k0 = ks*16 + (lane & 3)*2;
      float w00 = __ldg(wr + k0),     w01 = __ldg(wr + k0 + 1);
      float w10 = __ldg(wr + k0 + 8), w11 = __ldg(wr + k0 + 9);
      if (is_lo) {
        w00 -= __bfloat162float(__float2bfloat16_rn(w00));
        w01 -= __bfloat162float(__float2bfloat16_rn(w01));
        w10 -= __bfloat162float(__float2bfloat16_rn(w10));
        w11 -= __bfloat162float(__float2bfloat16_rn(w11));
      }
      bf0[ks] = pk2(w00, w01);
      bf1[ks] = pk2(w10, w11);
    }
  }

  // ---- zero s tiles (s[-1] = 0) ----
  for (int i = tid; i < 8320; i += NTHR) ((uint32_t*)smc)[i] = 0u;
  __syncthreads();

  // ldmatrix base address for this lane (rows 0-15, col-halves by lane>=16)
  const uint32_t aH = smb + SS_HI_B + (uint32_t)(lane & 15)*1040
                    + (uint32_t)((lane >> 4) & 1)*16;
  const uint32_t aL = aH + SS_LO_B;

  // update mapping (warps 0-7): lane owns (r, hh), (r, hh+1), (r+8, hh), (r+8, hh+1)
  const int r  = lane >> 2;
  const int hh = h0 + w*8 + (lane & 3)*2;
  float2 bin = make_float2(0.f, 0.f);
  if (w < 8) bin = *(const float2*)(b_in + hh);

  // readout mapping (warps 8-9 write out): oc = (w-8)*8 + (lane&3)*2
  const int oc = ((w - 8) & 1)*8 + (lane & 3)*2;
  float2 bo2 = make_float2(0.f, 0.f);
  if (w >= 8 && w < 10) bo2 = make_float2(__ldg(b_out + o0 + oc),
                                          __ldg(b_out + o0 + oc + 1));

  float v[4]  = {0.f,0.f,0.f,0.f};
  float a0s[4] = {0.f,0.f,0.f,0.f};
  float a1s[4] = {0.f,0.f,0.f,0.f};
  float sp[4] = {0.f,0.f,0.f,0.f};

  for (int t = 0; t <= T_STEPS; ++t) {
    // xp prefetch for the update (warps 0-7)
    float2 xq0 = make_float2(0.f, 0.f), xq1 = make_float2(0.f, 0.f);
    if (w < 8 && t < T_STEPS) {
      xq0 = __ldcg((const float2*)(g_xp + ((size_t)t*BATCH + b0 + r)*NHID + hh));
      xq1 = __ldcg((const float2*)(g_xp + ((size_t)t*BATCH + b0 + r + 8)*NHID + hh));
    }

    // ---- GEMM: D[16b, 8n] = W_slice @ (s_hi + s_lo), k = 512 ----
    float dh[4] = {0.f,0.f,0.f,0.f};
    float dl[4] = {0.f,0.f,0.f,0.f};
    #pragma unroll
    for (int ks = 0; ks < 32; ++ks) {
      uint32_t fa0, fa1, fa2, fa3;
      LDSM4(fa0, fa1, fa2, fa3, aH + (uint32_t)ks*32);
      MMA16816(dh, fa0, fa1, fa2, fa3, bf0[ks], bf1[ks]);
      uint32_t fb0, fb1, fb2, fb3;
      LDSM4(fb0, fb1, fb2, fb3, aL + (uint32_t)ks*32);
      MMA16816(dl, fb0, fb1, fb2, fb3, bf0[ks], bf1[ks]);
    }
    float d0 = dh[0] + dl[0], d1 = dh[1] + dl[1];
    float d2 = dh[2] + dl[2], d3 = dh[3] + dl[3];

    // ---- readout-lo exchange (warps 10-11 -> smem) ----
    if (w >= 10) {
      int c = (w - 10)*8 + (lane & 3)*2;
      olo[r*18 + c]           = d0;
      olo[r*18 + c + 1]       = d1;
      olo[(r + 8)*18 + c]     = d2;
      olo[(r + 8)*18 + c + 1] = d3;
    }
    __syncthreads();

    // ---- out[t-1] = o_hi + o_lo + b_out (warps 8-9) ----
    if (t >= 1 && w >= 8 && w < 10) {
      float* op = out + (size_t)(t - 1)*BATCH*NOUT + (size_t)(b0 + r)*NOUT + o0 + oc;
      *(float2*)op = make_float2(d0 + olo[r*18 + oc] + bo2.x,
                                 d1 + olo[r*18 + oc + 1] + bo2.y);
      float* op2 = op + 8*NOUT;
      *(float2*)op2 = make_float2(d2 + olo[(r + 8)*18 + oc] + bo2.x,
                                  d3 + olo[(r + 8)*18 + oc + 1] + bo2.y);
    }
    if (t == T_STEPS) break;

    // ---- GLIFR update (warps 0-7): 4 neurons from D fragment ----
    if (w < 8) {
      float yy[4] = {d0, d1, d2, d3};
      float xv[4] = {xq0.x, xq0.y, xq1.x, xq1.y};
      float bv[4] = {bin.x, bin.y, bin.x, bin.y};
      #pragma unroll
      for (int j = 0; j < 4; ++j) {
        float y  = 0.5f*(yy[j] + xv[j] + bv[j]);
        a0s[j] = fmaf(a0s[j],  0.85f, -0.05f*sp[j]);
        a1s[j] = fmaf(a1s[j], -0.5f,  -0.05f*sp[j]);
        float it = y + a0s[j] + a1s[j] + 700.0f;
        v[j]  = v[j]*0.99f*(1.0f - 0.05f*sp[j]) + 0.00101953125f*it;
        sp[j] = 20.0f / (1.0f + __expf(-v[j]*0.02f));
      }
      const int slot = t & 1;
      __stcg((float2*)&g_ring[slot][b0 + r][hh],     make_float2(sp[0], sp[1]));
      __stcg((float2*)&g_ring[slot][b0 + r + 8][hh], make_float2(sp[2], sp[3]));
    }

    grid_barrier(blk);

    // ---- restage: fp32 ring -> bf16 hi/lo s tiles ----
    {
      const int slot = t & 1;
      #pragma unroll
      for (int j = 0; j < 6; ++j) {
        int i = j*NTHR + tid;             // 0..2303, valid < 2048
        if (i < 2048) {
          int b = i >> 7, h4 = (i & 127)*4;
          float4 vv = __ldcg((const float4*)&g_ring[slot][b0 + b][h4]);
          float f[4] = {vv.x, vv.y, vv.z, vv.w};
          uint32_t hi01 = pk2(f[0], f[1]);
          uint32_t hi23 = pk2(f[2], f[3]);
          float r0 = f[0] - __bfloat162float(__float2bfloat16_rn(f[0]));
          float r1 = f[1] - __bfloat162float(__float2bfloat16_rn(f[1]));
          float r2 = f[2] - __bfloat162float(__float2bfloat16_rn(f[2]));
          float r3 = f[3] - __bfloat162float(__float2bfloat16_rn(f[3]));
          uint32_t lo01 = pk2(r0, r1);
          uint32_t lo23 = pk2(r2, r3);
          uint32_t boff = (uint32_t)b*1040 + (uint32_t)h4*2;
          *(uint2*)(smc + SS_HI_B + boff) = make_uint2(hi01, hi23);
          *(uint2*)(smc + SS_LO_B + boff) = make_uint2(lo01, lo23);
        }
      }
    }
    __syncthreads();
  }
}

extern "C" void kernel_launch(void* const* d_in, const int* in_sizes, int n_in,
                              void* d_out, int out_size) {
  const float* x     = (const float*)d_in[0];
  const float* W_in  = (const float*)d_in[1];
  const float* b_in  = (const float*)d_in[2];
  const float* W_rec = (const float*)d_in[3];
  const float* W_out = (const float*)d_in[4];
  const float* b_out = (const float*)d_in[5];
  float* out = (float*)d_out;

  cudaFuncSetAttribute(xp_kernel,
                       cudaFuncAttributeMaxDynamicSharedMemorySize, PSMEM_BYTES);
  cudaFuncSetAttribute(bnn_kernel,
                       cudaFuncAttributeMaxDynamicSharedMemorySize, SMEM_BYTES);

  dim3 pg((T_STEPS*BATCH)/PM, NHID/PN);   // (2000, 2)
  xp_kernel<<<pg, 512, PSMEM_BYTES>>>(x, W_in);
  bnn_kernel<<<NBLK, NTHR, SMEM_BYTES>>>(b_in, W_rec, W_out, b_out, out);
}

// round 12
// speedup vs baseline: 3.1286x; 1.5226x over previous
#include <cuda_runtime.h>
#include <cuda_bf16.h>
#include <cstdint>

#define T_STEPS 1000
#define BATCH   256
#define NIN     128
#define NHID    512
#define NOUT    128

#define NBLK 128
#define NTHR 384
#define BT 16      // batch rows per CTA
#define HT 64      // hidden cols per CTA

// smem: bf16 s tiles (hi, lo), row stride 520 bf16 = 1040 B
#define SROW 520
#define SS_HI_B 0
#define SS_LO_B (16*SROW*2)            // 16640
#define OLO_B   (2*16*SROW*2)          // 33280: readout-lo exchange [16][18] f32
#define SMEM_BYTES (OLO_B + 16*18*4)   // 34432 B

// precomputed input projection xp[t][b][h] (512 MB, device-static)
__device__ float g_xp[(size_t)T_STEPS*BATCH*NHID];
// bf16 hi/lo s rings (2 slots), b-major, u32 = 2 bf16 (even h first)
__device__ unsigned g_rh[2][BATCH][NHID/2];
__device__ unsigned g_rl[2][BATCH][NHID/2];
// per-btile barrier state (padded to separate cache lines)
__device__ unsigned g_bcnt[16*32];
__device__ unsigned g_bgen[16*32];

typedef unsigned long long u64;

__device__ __forceinline__ uint32_t smem_u32(const void* p) {
  uint32_t a;
  asm("{ .reg .u64 t; cvta.to.shared.u64 t, %1; cvt.u32.u64 %0, t; }"
      : "=r"(a) : "l"(p));
  return a;
}
__device__ __forceinline__ uint32_t pk2(float lo, float hi) {
  unsigned short a = __bfloat16_as_ushort(__float2bfloat16_rn(lo));
  unsigned short b = __bfloat16_as_ushort(__float2bfloat16_rn(hi));
  return (uint32_t)a | ((uint32_t)b << 16);
}
#define LDSM4(r0,r1,r2,r3,addr) \
  asm volatile("ldmatrix.sync.aligned.m8n8.x4.shared.b16 {%0,%1,%2,%3}, [%4];" \
    : "=r"(r0),"=r"(r1),"=r"(r2),"=r"(r3) : "r"(addr))
#define MMA16816(d, a0,a1,a2,a3, b0,b1) \
  asm volatile("mma.sync.aligned.m16n8k16.row.col.f32.bf16.bf16.f32 " \
    "{%0,%1,%2,%3}, {%4,%5,%6,%7}, {%8,%9}, {%0,%1,%2,%3};" \
    : "+f"((d)[0]),"+f"((d)[1]),"+f"((d)[2]),"+f"((d)[3]) \
    : "r"(a0),"r"(a1),"r"(a2),"r"(a3), "r"(b0),"r"(b1))

// per-btile barrier: only the 8 CTAs sharing a b-tile synchronize
__device__ __forceinline__ void btile_barrier(int btile) {
  __syncthreads();
  if (threadIdx.x == 0) {
    asm volatile("fence.acq_rel.gpu;" ::: "memory");
    unsigned my = *((volatile unsigned*)&g_bgen[btile*32]);
    if (atomicAdd(&g_bcnt[btile*32], 1u) == 7u) {
      atomicExch(&g_bcnt[btile*32], 0u);
      asm volatile("fence.acq_rel.gpu;" ::: "memory");
      atomicExch(&g_bgen[btile*32], my + 1u);
    }
    while (*((volatile unsigned*)&g_bgen[btile*32]) == my) { }
    asm volatile("fence.acq_rel.gpu;" ::: "memory");
  }
  __syncthreads();
}

// ---------------- pre-pass: xp = x @ W_in^T via mma.sync --------------------
// grid (2000, 4): 128m x 128n tiles; 256 threads = 8 warps (2m x 4n).
#define XAST 136   // A-tile bf16 row stride (128 + 8)
#define XSMEM_BYTES (128*XAST*2)   // 34816 B

__global__ void __launch_bounds__(256, 1)
xp_kernel(const float* __restrict__ x, const float* __restrict__ W_in) {
  extern __shared__ char xsc[];
  const uint32_t smb = smem_u32(xsc);
  const int tid = threadIdx.x;
  const int m0 = blockIdx.x * 128;
  const int n0 = blockIdx.y * 128;
  const int w = tid >> 5, lane = tid & 31;
  const int wm = w >> 2, wn = w & 3;

  // load x tile [128m][128k] fp32 -> bf16 smem
  const float4* x4 = (const float4*)x;
  #pragma unroll
  for (int j = 0; j < 16; ++j) {
    int g = j*256 + tid;                 // 0..4095
    int row = g >> 5, c4 = g & 31;
    float4 vv = __ldg(x4 + (size_t)(m0 + row)*32 + c4);
    uint2 p = make_uint2(pk2(vv.x, vv.y), pk2(vv.z, vv.w));
    *(uint2*)(xsc + row*(XAST*2) + c4*8) = p;
  }

  // B fragments (W_in) in regs: warp covers n-cols n0+wn*32 .. +31
  uint32_t b0[4][8], b1[4][8];
  #pragma unroll
  for (int ni = 0; ni < 4; ++ni) {
    const float* wr = W_in + (size_t)(n0 + wn*32 + ni*8 + (lane >> 2))*NIN;
    #pragma unroll
    for (int ks = 0; ks < 8; ++ks) {
      int k0 = ks*16 + (lane & 3)*2;
      b0[ni][ks] = pk2(__ldg(wr + k0),     __ldg(wr + k0 + 1));
      b1[ni][ks] = pk2(__ldg(wr + k0 + 8), __ldg(wr + k0 + 9));
    }
  }
  __syncthreads();

  const uint32_t ab = smb + (uint32_t)(wm*64 + (lane & 15))*(XAST*2)
                    + (uint32_t)((lane >> 4) & 1)*16;
  float acc[4][4][4];
  #pragma unroll
  for (int mi = 0; mi < 4; ++mi)
    #pragma unroll
    for (int ni = 0; ni < 4; ++ni)
      #pragma unroll
      for (int q = 0; q < 4; ++q) acc[mi][ni][q] = 0.f;

  #pragma unroll
  for (int mi = 0; mi < 4; ++mi) {
    #pragma unroll
    for (int ks = 0; ks < 8; ++ks) {
      uint32_t a0, a1, a2, a3;
      LDSM4(a0, a1, a2, a3, ab + (uint32_t)mi*16*(XAST*2) + (uint32_t)ks*32);
      #pragma unroll
      for (int ni = 0; ni < 4; ++ni)
        MMA16816(acc[mi][ni], a0, a1, a2, a3, b0[ni][ks], b1[ni][ks]);
    }
  }

  const int r = lane >> 2, c2 = (lane & 3)*2;
  #pragma unroll
  for (int mi = 0; mi < 4; ++mi) {
    #pragma unroll
    for (int ni = 0; ni < 4; ++ni) {
      size_t row = (size_t)(m0 + wm*64 + mi*16 + r);
      size_t col = (size_t)(n0 + wn*32 + ni*8 + c2);
      *(float2*)(g_xp + row*NHID + col) = make_float2(acc[mi][ni][0], acc[mi][ni][1]);
      *(float2*)(g_xp + (row + 8)*NHID + col) = make_float2(acc[mi][ni][2], acc[mi][ni][3]);
    }
  }
}

// ---------------- main persistent recurrent kernel (mma.sync HMMA) ----------
__global__ void __launch_bounds__(NTHR, 1)
bnn_kernel(const float* __restrict__ b_in,  // [NHID]
           const float* __restrict__ W_rec, // [NHID, NHID]
           const float* __restrict__ W_out, // [NOUT, NHID]
           const float* __restrict__ b_out, // [NOUT]
           float* __restrict__ out)         // [T, B, NOUT]
{
  extern __shared__ char smc[];
  const uint32_t smb = smem_u32(smc);
  float* olo = (float*)(smc + OLO_B);   // [16][18]

  const int tid = threadIdx.x;
  const int blk = blockIdx.x;
  const int btile = blk >> 3;           // 16 b-tiles (independent groups)
  const int htile = blk & 7;            // 8  h-tiles
  const int b0 = btile * BT;
  const int h0 = htile * HT;
  const int o0 = htile * 16;
  const int w  = tid >> 5;              // 0..11
  const int lane = tid & 31;

  // ---- B fragments in registers; warp covers n-slice w*8 ----
  // n 0-63: W_rec; n 64-79: W_out hi; n 80-95: W_out lo
  uint32_t bf0[32], bf1[32];
  {
    const int nn = w*8 + (lane >> 2);
    const float* wr;
    bool is_lo = false;
    if (nn < 64) wr = W_rec + (size_t)(h0 + nn)*NHID;
    else if (nn < 80) wr = W_out + (size_t)(o0 + nn - 64)*NHID;
    else { wr = W_out + (size_t)(o0 + nn - 80)*NHID; is_lo = true; }
    #pragma unroll
    for (int ks = 0; ks < 32; ++ks) {
      int k0 = ks*16 + (lane & 3)*2;
      float w00 = __ldg(wr + k0),     w01 = __ldg(wr + k0 + 1);
      float w10 = __ldg(wr + k0 + 8), w11 = __ldg(wr + k0 + 9);
      if (is_lo) {
        w00 -= __bfloat162float(__float2bfloat16_rn(w00));
        w01 -= __bfloat162float(__float2bfloat16_rn(w01));
        w10 -= __bfloat162float(__float2bfloat16_rn(w10));
        w11 -= __bfloat162float(__float2bfloat16_rn(w11));
      }
      bf0[ks] = pk2(w00, w01);
      bf1[ks] = pk2(w10, w11);
    }
  }

  // ---- zero s tiles (s[-1] = 0) ----
  for (int i = tid; i < 8320; i += NTHR) ((uint32_t*)smc)[i] = 0u;
  __syncthreads();

  const uint32_t aH = smb + SS_HI_B + (uint32_t)(lane & 15)*1040
                    + (uint32_t)((lane >> 4) & 1)*16;
  const uint32_t aL = aH + SS_LO_B;

  // update mapping (warps 0-7)
  const int r  = lane >> 2;
  const int hh = h0 + w*8 + (lane & 3)*2;
  float2 bin = make_float2(0.f, 0.f);
  if (w < 8) bin = *(const float2*)(b_in + hh);

  // readout mapping (warps 8-9 write out)
  const int oc = ((w - 8) & 1)*8 + (lane & 3)*2;
  float2 bo2 = make_float2(0.f, 0.f);
  if (w >= 8 && w < 10) bo2 = make_float2(__ldg(b_out + o0 + oc),
                                          __ldg(b_out + o0 + oc + 1));

  float v[4]  = {0.f,0.f,0.f,0.f};
  float a0s[4] = {0.f,0.f,0.f,0.f};
  float a1s[4] = {0.f,0.f,0.f,0.f};
  float sp[4] = {0.f,0.f,0.f,0.f};

  for (int t = 0; t <= T_STEPS; ++t) {
    float d0, d1, d2, d3;

    if (w < 8) {
      // xp prefetch (consumed at update)
      float2 xq0 = make_float2(0.f, 0.f), xq1 = make_float2(0.f, 0.f);
      if (t < T_STEPS) {
        xq0 = __ldcg((const float2*)(g_xp + ((size_t)t*BATCH + b0 + r)*NHID + hh));
        xq1 = __ldcg((const float2*)(g_xp + ((size_t)t*BATCH + b0 + r + 8)*NHID + hh));
      }
      // ---- update GEMM: W_rec @ s_hi only (32 MMAs, 2 chains) ----
      float dA[4] = {0.f,0.f,0.f,0.f};
      float dB[4] = {0.f,0.f,0.f,0.f};
      #pragma unroll
      for (int ks = 0; ks < 32; ks += 2) {
        uint32_t fa0, fa1, fa2, fa3;
        LDSM4(fa0, fa1, fa2, fa3, aH + (uint32_t)ks*32);
        MMA16816(dA, fa0, fa1, fa2, fa3, bf0[ks], bf1[ks]);
        uint32_t fb0, fb1, fb2, fb3;
        LDSM4(fb0, fb1, fb2, fb3, aH + (uint32_t)(ks + 1)*32);
        MMA16816(dB, fb0, fb1, fb2, fb3, bf0[ks + 1], bf1[ks + 1]);
      }
      d0 = dA[0] + dB[0]; d1 = dA[1] + dB[1];
      d2 = dA[2] + dB[2]; d3 = dA[3] + dB[3];

      if (t < T_STEPS) {
        // ---- GLIFR update ----
        float yy[4] = {d0, d1, d2, d3};
        float xv[4] = {xq0.x, xq0.y, xq1.x, xq1.y};
        float bv[4] = {bin.x, bin.y, bin.x, bin.y};
        #pragma unroll
        for (int j = 0; j < 4; ++j) {
          float y  = 0.5f*(yy[j] + xv[j] + bv[j]);
          a0s[j] = fmaf(a0s[j],  0.85f, -0.05f*sp[j]);
          a1s[j] = fmaf(a1s[j], -0.5f,  -0.05f*sp[j]);
          float it = y + a0s[j] + a1s[j] + 700.0f;
          v[j]  = v[j]*0.99f*(1.0f - 0.05f*sp[j]) + 0.00101953125f*it;
          sp[j] = 20.0f / (1.0f + __expf(-v[j]*0.02f));
        }
        // publish bf16 hi/lo (conversion on producer side)
        const int slot = t & 1;
        float h0f = __bfloat162float(__float2bfloat16_rn(sp[0]));
        float h1f = __bfloat162float(__float2bfloat16_rn(sp[1]));
        float h2f = __bfloat162float(__float2bfloat16_rn(sp[2]));
        float h3f = __bfloat162float(__float2bfloat16_rn(sp[3]));
        __stcg(&g_rh[slot][b0 + r][hh >> 1],     pk2(sp[0], sp[1]));
        __stcg(&g_rh[slot][b0 + r + 8][hh >> 1], pk2(sp[2], sp[3]));
        __stcg(&g_rl[slot][b0 + r][hh >> 1],     pk2(sp[0] - h0f, sp[1] - h1f));
        __stcg(&g_rl[slot][b0 + r + 8][hh >> 1], pk2(sp[2] - h2f, sp[3] - h3f));
      }
    } else if (w < 10) {
      // ---- readout hi GEMM: W_out_hi @ (s_hi + s_lo) ----
      float dh[4] = {0.f,0.f,0.f,0.f};
      float dl[4] = {0.f,0.f,0.f,0.f};
      #pragma unroll
      for (int ks = 0; ks < 32; ++ks) {
        uint32_t fa0, fa1, fa2, fa3;
        LDSM4(fa0, fa1, fa2, fa3, aH + (uint32_t)ks*32);
        MMA16816(dh, fa0, fa1, fa2, fa3, bf0[ks], bf1[ks]);
        uint32_t fb0, fb1, fb2, fb3;
        LDSM4(fb0, fb1, fb2, fb3, aL + (uint32_t)ks*32);
        MMA16816(dl, fb0, fb1, fb2, fb3, bf0[ks], bf1[ks]);
      }
      d0 = dh[0] + dl[0]; d1 = dh[1] + dl[1];
      d2 = dh[2] + dl[2]; d3 = dh[3] + dl[3];
      asm volatile("bar.sync 8, 128;" ::: "memory");
      // out[t-1] = o_hi + o_lo + b_out
      if (t >= 1) {
        float* op = out + (size_t)(t - 1)*BATCH*NOUT + (size_t)(b0 + r)*NOUT + o0 + oc;
        *(float2*)op = make_float2(d0 + olo[r*18 + oc] + bo2.x,
                                   d1 + olo[r*18 + oc + 1] + bo2.y);
        float* op2 = op + 8*NOUT;
        *(float2*)op2 = make_float2(d2 + olo[(r + 8)*18 + oc] + bo2.x,
                                    d3 + olo[(r + 8)*18 + oc + 1] + bo2.y);
      }
    } else {
      // ---- readout lo GEMM: W_out_lo @ s_hi (32 MMAs, 2 chains) ----
      float dA[4] = {0.f,0.f,0.f,0.f};
      float dB[4] = {0.f,0.f,0.f,0.f};
      #pragma unroll
      for (int ks = 0; ks < 32; ks += 2) {
        uint32_t fa0, fa1, fa2, fa3;
        LDSM4(fa0, fa1, fa2, fa3, aH + (uint32_t)ks*32);
        MMA16816(dA, fa0, fa1, fa2, fa3, bf0[ks], bf1[ks]);
        uint32_t fb0, fb1, fb2, fb3;
        LDSM4(fb0, fb1, fb2, fb3, aH + (uint32_t)(ks + 1)*32);
        MMA16816(dB, fb0, fb1, fb2, fb3, bf0[ks + 1], bf1[ks + 1]);
      }
      d0 = dA[0] + dB[0]; d1 = dA[1] + dB[1];
      d2 = dA[2] + dB[2]; d3 = dA[3] + dB[3];
      int c = (w - 10)*8 + (lane & 3)*2;
      olo[r*18 + c]           = d0;
      olo[r*18 + c + 1]       = d1;
      olo[(r + 8)*18 + c]     = d2;
      olo[(r + 8)*18 + c + 1] = d3;
      asm volatile("bar.sync 8, 128;" ::: "memory");
    }

    if (t == T_STEPS) break;

    btile_barrier(btile);

    // ---- restage: bf16 rings -> smem tiles (pure copy) ----
    {
      const int slot = t & 1;
      #pragma unroll
      for (int j = 0; j < 6; ++j) {
        int i = j*NTHR + tid;             // 0..2303, valid < 2048
        if (i < 2048) {
          int half = i >> 10;             // 0 = hi, 1 = lo
          int ii = i & 1023;
          int b = ii >> 6, h8 = ii & 63;  // 8 bf16 per uint4
          const unsigned* src = half ? &g_rl[slot][b0 + b][h8*4]
                                     : &g_rh[slot][b0 + b][h8*4];
          uint4 vv = __ldcg((const uint4*)src);
          *(uint4*)(smc + (half ? SS_LO_B : SS_HI_B) + b*1040 + h8*16) = vv;
        }
      }
    }
    __syncthreads();
  }
}

extern "C" void kernel_launch(void* const* d_in, const int* in_sizes, int n_in,
                              void* d_out, int out_size) {
  const float* x     = (const float*)d_in[0];
  const float* W_in  = (const float*)d_in[1];
  const float* b_in  = (const float*)d_in[2];
  const float* W_rec = (const float*)d_in[3];
  const float* W_out = (const float*)d_in[4];
  const float* b_out = (const float*)d_in[5];
  float* out = (float*)d_out;

  cudaFuncSetAttribute(xp_kernel,
                       cudaFuncAttributeMaxDynamicSharedMemorySize, XSMEM_BYTES);
  cudaFuncSetAttribute(bnn_kernel,
                       cudaFuncAttributeMaxDynamicSharedMemorySize, SMEM_BYTES);

  dim3 pg((T_STEPS*BATCH)/128, NHID/128);   // (2000, 4)
  xp_kernel<<<pg, 256, XSMEM_BYTES>>>(x, W_in);
  bnn_kernel<<<NBLK, NTHR, SMEM_BYTES>>>(b_in, W_rec, W_out, b_out, out);
}

// round 13
// speedup vs baseline: 3.4329x; 1.0973x over previous
#include <cuda_runtime.h>
#include <cuda_bf16.h>
#include <cstdint>

#define T_STEPS 1000
#define BATCH   256
#define NIN     128
#define NHID    512
#define NOUT    128

#define NBLK 128
#define NTHR 384
#define BT 16      // batch rows per CTA
#define HT 64      // hidden cols per CTA

// smem: bf16 s tiles (hi, lo), row stride 520 bf16 = 1040 B
#define SROW 520
#define SS_HI_B 0
#define SS_LO_B 16640                  // 16*1040
#define XT_B    33280                  // 2 buffers x 16 rows x 272 B = 8704
#define WIN_B   41984                  // W_in fragments: 8w x 8ks x 32lane x 8B = 16384
#define OLO_B   58368                  // readout-lo exchange [16][18] f32
#define SMEM_BYTES (OLO_B + 16*18*4)   // 59520 B

// bf16 hi/lo s rings (2 slots), b-major, u32 = 2 bf16
__device__ unsigned g_rh[2][BATCH][NHID/2];
__device__ unsigned g_rl[2][BATCH][NHID/2];
// flag barrier state: flags[btile][htile] (128B line per btile)
__device__ unsigned g_flag[16][32];
// closing atomic barrier (generation style; replay-monotonic)
__device__ unsigned g_bcnt[16*32];
__device__ unsigned g_bgen[16*32];

typedef unsigned long long u64;

__device__ __forceinline__ uint32_t smem_u32(const void* p) {
  uint32_t a;
  asm("{ .reg .u64 t; cvta.to.shared.u64 t, %1; cvt.u32.u64 %0, t; }"
      : "=r"(a) : "l"(p));
  return a;
}
__device__ __forceinline__ uint32_t pk2(float lo, float hi) {
  unsigned short a = __bfloat16_as_ushort(__float2bfloat16_rn(lo));
  unsigned short b = __bfloat16_as_ushort(__float2bfloat16_rn(hi));
  return (uint32_t)a | ((uint32_t)b << 16);
}
#define LDSM4(r0,r1,r2,r3,addr) \
  asm volatile("ldmatrix.sync.aligned.m8n8.x4.shared.b16 {%0,%1,%2,%3}, [%4];" \
    : "=r"(r0),"=r"(r1),"=r"(r2),"=r"(r3) : "r"(addr))
#define MMA16816(d, a0,a1,a2,a3, b0,b1) \
  asm volatile("mma.sync.aligned.m16n8k16.row.col.f32.bf16.bf16.f32 " \
    "{%0,%1,%2,%3}, {%4,%5,%6,%7}, {%8,%9}, {%0,%1,%2,%3};" \
    : "+f"((d)[0]),"+f"((d)[1]),"+f"((d)[2]),"+f"((d)[3]) \
    : "r"(a0),"r"(a1),"r"(a2),"r"(a3), "r"(b0),"r"(b1))

__global__ void __launch_bounds__(NTHR, 1)
bnn_kernel(const float* __restrict__ x,     // [T, B, NIN]
           const float* __restrict__ W_in,  // [NHID, NIN]
           const float* __restrict__ b_in,  // [NHID]
           const float* __restrict__ W_rec, // [NHID, NHID]
           const float* __restrict__ W_out, // [NOUT, NHID]
           const float* __restrict__ b_out, // [NOUT]
           float* __restrict__ out)         // [T, B, NOUT]
{
  extern __shared__ char smc[];
  const uint32_t smb = smem_u32(smc);
  float* olo = (float*)(smc + OLO_B);   // [16][18]

  const int tid = threadIdx.x;
  const int blk = blockIdx.x;
  const int btile = blk >> 3;           // 16 independent b-tiles
  const int htile = blk & 7;            // 8 h-tiles = barrier group members
  const int b0 = btile * BT;
  const int h0 = htile * HT;
  const int o0 = htile * 16;
  const int w  = tid >> 5;              // 0..11
  const int lane = tid & 31;

  // ---- B fragments (W_rec / W_out hi / W_out lo) in registers ----
  uint32_t bf0[32], bf1[32];
  {
    const int nn = w*8 + (lane >> 2);
    const float* wr;
    bool is_lo = false;
    if (nn < 64) wr = W_rec + (size_t)(h0 + nn)*NHID;
    else if (nn < 80) wr = W_out + (size_t)(o0 + nn - 64)*NHID;
    else { wr = W_out + (size_t)(o0 + nn - 80)*NHID; is_lo = true; }
    #pragma unroll
    for (int ks = 0; ks < 32; ++ks) {
      int k0 = ks*16 + (lane & 3)*2;
      float w00 = __ldg(wr + k0),     w01 = __ldg(wr + k0 + 1);
      float w10 = __ldg(wr + k0 + 8), w11 = __ldg(wr + k0 + 9);
      if (is_lo) {
        w00 -= __bfloat162float(__float2bfloat16_rn(w00));
        w01 -= __bfloat162float(__float2bfloat16_rn(w01));
        w10 -= __bfloat162float(__float2bfloat16_rn(w10));
        w11 -= __bfloat162float(__float2bfloat16_rn(w11));
      }
      bf0[ks] = pk2(w00, w01);
      bf1[ks] = pk2(w10, w11);
    }
  }

  // ---- W_in B-fragments into smem (update warps own their slice) ----
  if (w < 8) {
    const float* wr = W_in + (size_t)(h0 + w*8 + (lane >> 2))*NIN;
    #pragma unroll
    for (int ks = 0; ks < 8; ++ks) {
      int k0 = ks*16 + (lane & 3)*2;
      uint32_t lo = pk2(__ldg(wr + k0),     __ldg(wr + k0 + 1));
      uint32_t hi = pk2(__ldg(wr + k0 + 8), __ldg(wr + k0 + 9));
      *(uint2*)(smc + WIN_B + (size_t)((w*8 + ks)*32 + lane)*8) = make_uint2(lo, hi);
    }
  }

  // ---- zero s tiles (s[-1] = 0); stage x[0] -> XT[0] ----
  for (int i = tid; i < 8320; i += NTHR) ((uint32_t*)smc)[i] = 0u;
  {
    const float4* xr = (const float4*)x + (size_t)b0*32;
    for (int i = tid; i < 512; i += NTHR) {
      int row = i >> 5, c4 = i & 31;
      float4 vv = __ldg(xr + row*32 + c4);
      *(uint2*)(smc + XT_B + row*272 + c4*8) = make_uint2(pk2(vv.x, vv.y), pk2(vv.z, vv.w));
    }
  }
  __syncthreads();

  const uint32_t aH = smb + SS_HI_B + (uint32_t)(lane & 15)*1040
                    + (uint32_t)((lane >> 4) & 1)*16;
  const uint32_t aL = aH + (SS_LO_B - SS_HI_B);
  const uint32_t aX0 = smb + XT_B + (uint32_t)(lane & 15)*272
                     + (uint32_t)((lane >> 4) & 1)*16;
  const char* winp = smc + WIN_B + (size_t)(w*8*32 + lane)*8;

  // update mapping (warps 0-7)
  const int r  = lane >> 2;
  const int hh = h0 + w*8 + (lane & 3)*2;
  float2 bin = make_float2(0.f, 0.f);
  if (w < 8) bin = *(const float2*)(b_in + hh);

  // readout mapping (warps 8-9 write out)
  const int oc = ((w - 8) & 1)*8 + (lane & 3)*2;
  float2 bo2 = make_float2(0.f, 0.f);
  if (w >= 8 && w < 10) bo2 = make_float2(__ldg(b_out + o0 + oc),
                                          __ldg(b_out + o0 + oc + 1));

  float v[4]  = {0.f,0.f,0.f,0.f};
  float a0s[4] = {0.f,0.f,0.f,0.f};
  float a1s[4] = {0.f,0.f,0.f,0.f};
  float sp[4] = {0.f,0.f,0.f,0.f};

  for (int t = 0; t <= T_STEPS; ++t) {
    if (w < 8) {
      if (t < T_STEPS) {
        // ---- update GEMM: W_rec @ s_hi (4 chains) + W_in @ x[t] (1 chain) ----
        float dA[4] = {0.f,0.f,0.f,0.f}, dB[4] = {0.f,0.f,0.f,0.f};
        float dC[4] = {0.f,0.f,0.f,0.f}, dD[4] = {0.f,0.f,0.f,0.f};
        float dX[4] = {0.f,0.f,0.f,0.f};
        #pragma unroll
        for (int ks = 0; ks < 32; ks += 4) {
          uint32_t f0, f1, f2, f3;
          LDSM4(f0, f1, f2, f3, aH + (uint32_t)ks*32);
          MMA16816(dA, f0, f1, f2, f3, bf0[ks], bf1[ks]);
          uint32_t g0, g1, g2, g3;
          LDSM4(g0, g1, g2, g3, aH + (uint32_t)(ks + 1)*32);
          MMA16816(dB, g0, g1, g2, g3, bf0[ks + 1], bf1[ks + 1]);
          uint32_t h0r, h1r, h2r, h3r;
          LDSM4(h0r, h1r, h2r, h3r, aH + (uint32_t)(ks + 2)*32);
          MMA16816(dC, h0r, h1r, h2r, h3r, bf0[ks + 2], bf1[ks + 2]);
          uint32_t i0, i1, i2, i3;
          LDSM4(i0, i1, i2, i3, aH + (uint32_t)(ks + 3)*32);
          MMA16816(dD, i0, i1, i2, i3, bf0[ks + 3], bf1[ks + 3]);
        }
        {
          const uint32_t aX = aX0 + (uint32_t)(t & 1)*4352;
          #pragma unroll
          for (int ks = 0; ks < 8; ++ks) {
            uint2 wf = *(const uint2*)(winp + ks*256);
            uint32_t f0, f1, f2, f3;
            LDSM4(f0, f1, f2, f3, aX + (uint32_t)ks*32);
            MMA16816(dX, f0, f1, f2, f3, wf.x, wf.y);
          }
        }
        float yy[4], xv[4];
        #pragma unroll
        for (int j = 0; j < 4; ++j) {
          yy[j] = dA[j] + dB[j] + dC[j] + dD[j];
          xv[j] = dX[j];
        }
        // ---- GLIFR update ----
        float bv[4] = {bin.x, bin.y, bin.x, bin.y};
        #pragma unroll
        for (int j = 0; j < 4; ++j) {
          float y  = 0.5f*(yy[j] + xv[j] + bv[j]);
          a0s[j] = fmaf(a0s[j],  0.85f, -0.05f*sp[j]);
          a1s[j] = fmaf(a1s[j], -0.5f,  -0.05f*sp[j]);
          float it = y + a0s[j] + a1s[j] + 700.0f;
          v[j]  = v[j]*0.99f*(1.0f - 0.05f*sp[j]) + 0.00101953125f*it;
          sp[j] = 20.0f / (1.0f + __expf(-v[j]*0.02f));
        }
        // publish bf16 hi/lo
        const int slot = t & 1;
        float h0f = __bfloat162float(__float2bfloat16_rn(sp[0]));
        float h1f = __bfloat162float(__float2bfloat16_rn(sp[1]));
        float h2f = __bfloat162float(__float2bfloat16_rn(sp[2]));
        float h3f = __bfloat162float(__float2bfloat16_rn(sp[3]));
        __stcg(&g_rh[slot][b0 + r][hh >> 1],     pk2(sp[0], sp[1]));
        __stcg(&g_rh[slot][b0 + r + 8][hh >> 1], pk2(sp[2], sp[3]));
        __stcg(&g_rl[slot][b0 + r][hh >> 1],     pk2(sp[0] - h0f, sp[1] - h1f));
        __stcg(&g_rl[slot][b0 + r + 8][hh >> 1], pk2(sp[2] - h2f, sp[3] - h3f));
      }
    } else if (w < 10) {
      // ---- readout hi GEMM: W_out_hi @ (s_hi + s_lo), 4 chains ----
      float dh0[4] = {0.f,0.f,0.f,0.f}, dh1[4] = {0.f,0.f,0.f,0.f};
      float dl0[4] = {0.f,0.f,0.f,0.f}, dl1[4] = {0.f,0.f,0.f,0.f};
      #pragma unroll
      for (int ks = 0; ks < 32; ks += 2) {
        uint32_t f0, f1, f2, f3;
        LDSM4(f0, f1, f2, f3, aH + (uint32_t)ks*32);
        MMA16816(dh0, f0, f1, f2, f3, bf0[ks], bf1[ks]);
        uint32_t g0, g1, g2, g3;
        LDSM4(g0, g1, g2, g3, aH + (uint32_t)(ks + 1)*32);
        MMA16816(dh1, g0, g1, g2, g3, bf0[ks + 1], bf1[ks + 1]);
        uint32_t h0r, h1r, h2r, h3r;
        LDSM4(h0r, h1r, h2r, h3r, aL + (uint32_t)ks*32);
        MMA16816(dl0, h0r, h1r, h2r, h3r, bf0[ks], bf1[ks]);
        uint32_t i0, i1, i2, i3;
        LDSM4(i0, i1, i2, i3, aL + (uint32_t)(ks + 1)*32);
        MMA16816(dl1, i0, i1, i2, i3, bf0[ks + 1], bf1[ks + 1]);
      }
      float d0 = dh0[0] + dh1[0] + dl0[0] + dl1[0];
      float d1 = dh0[1] + dh1[1] + dl0[1] + dl1[1];
      float d2 = dh0[2] + dh1[2] + dl0[2] + dl1[2];
      float d3 = dh0[3] + dh1[3] + dl0[3] + dl1[3];
      asm volatile("bar.sync 8, 128;" ::: "memory");
      if (t >= 1) {
        float* op = out + (size_t)(t - 1)*BATCH*NOUT + (size_t)(b0 + r)*NOUT + o0 + oc;
        *(float2*)op = make_float2(d0 + olo[r*18 + oc] + bo2.x,
                                   d1 + olo[r*18 + oc + 1] + bo2.y);
        float* op2 = op + 8*NOUT;
        *(float2*)op2 = make_float2(d2 + olo[(r + 8)*18 + oc] + bo2.x,
                                    d3 + olo[(r + 8)*18 + oc + 1] + bo2.y);
      }
    } else {
      // ---- readout lo GEMM: W_out_lo @ s_hi, 4 chains ----
      float dA[4] = {0.f,0.f,0.f,0.f}, dB[4] = {0.f,0.f,0.f,0.f};
      float dC[4] = {0.f,0.f,0.f,0.f}, dD[4] = {0.f,0.f,0.f,0.f};
      #pragma unroll
      for (int ks = 0; ks < 32; ks += 4) {
        uint32_t f0, f1, f2, f3;
        LDSM4(f0, f1, f2, f3, aH + (uint32_t)ks*32);
        MMA16816(dA, f0, f1, f2, f3, bf0[ks], bf1[ks]);
        uint32_t g0, g1, g2, g3;
        LDSM4(g0, g1, g2, g3, aH + (uint32_t)(ks + 1)*32);
        MMA16816(dB, g0, g1, g2, g3, bf0[ks + 1], bf1[ks + 1]);
        uint32_t h0r, h1r, h2r, h3r;
        LDSM4(h0r, h1r, h2r, h3r, aH + (uint32_t)(ks + 2)*32);
        MMA16816(dC, h0r, h1r, h2r, h3r, bf0[ks + 2], bf1[ks + 2]);
        uint32_t i0, i1, i2, i3;
        LDSM4(i0, i1, i2, i3, aH + (uint32_t)(ks + 3)*32);
        MMA16816(dD, i0, i1, i2, i3, bf0[ks + 3], bf1[ks + 3]);
      }
      int c = (w - 10)*8 + (lane & 3)*2;
      olo[r*18 + c]           = dA[0] + dB[0] + dC[0] + dD[0];
      olo[r*18 + c + 1]       = dA[1] + dB[1] + dC[1] + dD[1];
      olo[(r + 8)*18 + c]     = dA[2] + dB[2] + dC[2] + dD[2];
      olo[(r + 8)*18 + c + 1] = dA[3] + dB[3] + dC[3] + dD[3];
      asm volatile("bar.sync 8, 128;" ::: "memory");
    }

    if (t == T_STEPS) break;

    // ---- stage x[t+1] into XT[(t+1)&1] (pre-barrier: overlaps publish) ----
    {
      int tn = (t + 1 < T_STEPS) ? t + 1 : (T_STEPS - 1);
      const float4* xr = (const float4*)(x + (size_t)tn*BATCH*NIN) + (size_t)b0*32;
      char* dst = smc + XT_B + ((t + 1) & 1)*4352;
      for (int i = tid; i < 512; i += NTHR) {
        int row = i >> 5, c4 = i & 31;
        float4 vv = __ldg(xr + row*32 + c4);
        *(uint2*)(dst + row*272 + c4*8) = make_uint2(pk2(vv.x, vv.y), pk2(vv.z, vv.w));
      }
    }

    // ---- flag-exchange barrier over this btile's 8 CTAs ----
    __syncthreads();
    if (tid == 0) {
      asm volatile("fence.acq_rel.gpu;" ::: "memory");
      unsigned want = (unsigned)(t + 1);
      __stcg(&g_flag[btile][htile], want);
      const uint4* fp = (const uint4*)&g_flag[btile][0];
      for (;;) {
        uint4 f0 = __ldcg(fp);
        uint4 f1 = __ldcg(fp + 1);
        if (f0.x >= want && f0.y >= want && f0.z >= want && f0.w >= want &&
            f1.x >= want && f1.y >= want && f1.z >= want && f1.w >= want) break;
      }
      asm volatile("fence.acq_rel.gpu;" ::: "memory");
    }
    __syncthreads();

    // ---- restage: bf16 rings -> smem s tiles (pure copy) ----
    {
      const int slot = t & 1;
      #pragma unroll
      for (int j = 0; j < 6; ++j) {
        int i = j*NTHR + tid;             // 0..2303, valid < 2048
        if (i < 2048) {
          int half = i >> 10;             // 0 = hi, 1 = lo
          int ii = i & 1023;
          int b = ii >> 6, h8 = ii & 63;
          const unsigned* src = half ? &g_rl[slot][b0 + b][h8*4]
                                     : &g_rh[slot][b0 + b][h8*4];
          uint4 vv = __ldcg((const uint4*)src);
          *(uint4*)(smc + (half ? SS_LO_B : SS_HI_B) + b*1040 + h8*16) = vv;
        }
      }
    }
    __syncthreads();
  }

  // ---- closing barrier + flag reset (replay determinism) ----
  __syncthreads();
  if (tid == 0) {
    unsigned my = *((volatile unsigned*)&g_bgen[btile*32]);
    if (atomicAdd(&g_bcnt[btile*32], 1u) == 7u) {
      atomicExch(&g_bcnt[btile*32], 0u);
      atomicExch(&g_bgen[btile*32], my + 1u);
    }
    while (*((volatile unsigned*)&g_bgen[btile*32]) == my) { }
    __stcg(&g_flag[btile][htile], 0u);
  }
}

extern "C" void kernel_launch(void* const* d_in, const int* in_sizes, int n_in,
                              void* d_out, int out_size) {
  const float* x     = (const float*)d_in[0];
  const float* W_in  = (const float*)d_in[1];
  const float* b_in  = (const float*)d_in[2];
  const float* W_rec = (const float*)d_in[3];
  const float* W_out = (const float*)d_in[4];
  const float* b_out = (const float*)d_in[5];
  float* out = (float*)d_out;

  cudaFuncSetAttribute(bnn_kernel,
                       cudaFuncAttributeMaxDynamicSharedMemorySize, SMEM_BYTES);
  bnn_kernel<<<NBLK, NTHR, SMEM_BYTES>>>(x, W_in, b_in, W_rec, W_out, b_out, out);
}

// round 15
// speedup vs baseline: 3.9401x; 1.1478x over previous
#include <cuda_runtime.h>
#include <cuda_bf16.h>
#include <cstdint>

#define T_STEPS 1000
#define BATCH   256
#define NIN     128
#define NHID    512
#define NOUT    128

#define NBLK 128
#define NTHR 384
#define BT 16      // batch rows per CTA
#define HT 64      // hidden cols per CTA

// smem: double-buffered bf16 s tiles (hi, lo), row stride 520 bf16 = 1040 B
#define SBUF0   0
#define SBUF1   33280                  // buf stride: 2*16*1040 (hi at +0, lo at +16640)
#define SLO_OFF 16640
#define XT_B    66560                  // 2 buffers x 16 rows x 272 B = 8704
#define WIN_B   75264                  // W_in fragments: 8w x 8ks x 32lane x 8B = 16384
#define OLO_B   91648                  // readout-lo exchange [16][18] f32 = 1152
#define SMEM_BYTES (OLO_B + 16*18*4)   // 92800 B

// bf16 hi/lo s rings (2 slots), b-major, u32 = 2 bf16
__device__ unsigned g_rh[2][BATCH][NHID/2];
__device__ unsigned g_rl[2][BATCH][NHID/2];
// flag barrier state: flags[btile][htile] (128B line per btile)
__device__ unsigned g_flag[16][32];
// closing atomic barrier (generation style; replay-monotonic)
__device__ unsigned g_bcnt[16*32];
__device__ unsigned g_bgen[16*32];

typedef unsigned long long u64;

__device__ __forceinline__ uint32_t smem_u32(const void* p) {
  uint32_t a;
  asm("{ .reg .u64 t; cvta.to.shared.u64 t, %1; cvt.u32.u64 %0, t; }"
      : "=r"(a) : "l"(p));
  return a;
}
__device__ __forceinline__ uint32_t pk2(float lo, float hi) {
  unsigned short a = __bfloat16_as_ushort(__float2bfloat16_rn(lo));
  unsigned short b = __bfloat16_as_ushort(__float2bfloat16_rn(hi));
  return (uint32_t)a | ((uint32_t)b << 16);
}
#define LDSM4(r0,r1,r2,r3,addr) \
  asm volatile("ldmatrix.sync.aligned.m8n8.x4.shared.b16 {%0,%1,%2,%3}, [%4];" \
    : "=r"(r0),"=r"(r1),"=r"(r2),"=r"(r3) : "r"(addr))
#define MMA16816(d, a0,a1,a2,a3, b0,b1) \
  asm volatile("mma.sync.aligned.m16n8k16.row.col.f32.bf16.bf16.f32 " \
    "{%0,%1,%2,%3}, {%4,%5,%6,%7}, {%8,%9}, {%0,%1,%2,%3};" \
    : "+f"((d)[0]),"+f"((d)[1]),"+f"((d)[2]),"+f"((d)[3]) \
    : "r"(a0),"r"(a1),"r"(a2),"r"(a3), "r"(b0),"r"(b1))

// acquire-correct flag poll: volatile L2 loads; fence before returning
__device__ __forceinline__ void poll_flags(const unsigned* fbase, unsigned want) {
  for (;;) {
    unsigned f0, f1, f2, f3, f4, f5, f6, f7;
    asm volatile("ld.global.cg.v4.u32 {%0,%1,%2,%3}, [%4];"
                 : "=r"(f0), "=r"(f1), "=r"(f2), "=r"(f3) : "l"(fbase));
    asm volatile("ld.global.cg.v4.u32 {%0,%1,%2,%3}, [%4];"
                 : "=r"(f4), "=r"(f5), "=r"(f6), "=r"(f7) : "l"(fbase + 4));
    if (f0 >= want && f1 >= want && f2 >= want && f3 >= want &&
        f4 >= want && f5 >= want && f6 >= want && f7 >= want) break;
  }
  asm volatile("fence.acq_rel.gpu;" ::: "memory");   // acquire
}

__global__ void __launch_bounds__(NTHR, 1)
bnn_kernel(const float* __restrict__ x,     // [T, B, NIN]
           const float* __restrict__ W_in,  // [NHID, NIN]
           const float* __restrict__ b_in,  // [NHID]
           const float* __restrict__ W_rec, // [NHID, NHID]
           const float* __restrict__ W_out, // [NOUT, NHID]
           const float* __restrict__ b_out, // [NOUT]
           float* __restrict__ out)         // [T, B, NOUT]
{
  extern __shared__ char smc[];
  const uint32_t smb = smem_u32(smc);
  float* olo = (float*)(smc + OLO_B);   // [16][18]

  const int tid = threadIdx.x;
  const int blk = blockIdx.x;
  const int btile = blk >> 3;           // 16 independent b-tiles
  const int htile = blk & 7;            // 8 h-tiles = barrier group members
  const int b0 = btile * BT;
  const int h0 = htile * HT;
  const int o0 = htile * 16;
  const int w  = tid >> 5;              // 0..11
  const int lane = tid & 31;

  // ---- B fragments (W_rec / W_out hi / W_out lo) in registers ----
  uint32_t bf0[32], bf1[32];
  {
    const int nn = w*8 + (lane >> 2);
    const float* wr;
    bool is_lo = false;
    if (nn < 64) wr = W_rec + (size_t)(h0 + nn)*NHID;
    else if (nn < 80) wr = W_out + (size_t)(o0 + nn - 64)*NHID;
    else { wr = W_out + (size_t)(o0 + nn - 80)*NHID; is_lo = true; }
    #pragma unroll
    for (int ks = 0; ks < 32; ++ks) {
      int k0 = ks*16 + (lane & 3)*2;
      float w00 = __ldg(wr + k0),     w01 = __ldg(wr + k0 + 1);
      float w10 = __ldg(wr + k0 + 8), w11 = __ldg(wr + k0 + 9);
      if (is_lo) {
        w00 -= __bfloat162float(__float2bfloat16_rn(w00));
        w01 -= __bfloat162float(__float2bfloat16_rn(w01));
        w10 -= __bfloat162float(__float2bfloat16_rn(w10));
        w11 -= __bfloat162float(__float2bfloat16_rn(w11));
      }
      bf0[ks] = pk2(w00, w01);
      bf1[ks] = pk2(w10, w11);
    }
  }

  // ---- W_in B-fragments into smem (update warps own their slice) ----
  if (w < 8) {
    const float* wr = W_in + (size_t)(h0 + w*8 + (lane >> 2))*NIN;
    #pragma unroll
    for (int ks = 0; ks < 8; ++ks) {
      int k0 = ks*16 + (lane & 3)*2;
      uint32_t lo = pk2(__ldg(wr + k0),     __ldg(wr + k0 + 1));
      uint32_t hi = pk2(__ldg(wr + k0 + 8), __ldg(wr + k0 + 9));
      *(uint2*)(smc + WIN_B + (size_t)((w*8 + ks)*32 + lane)*8) = make_uint2(lo, hi);
    }
  }

  // ---- zero s buffer 0 (s[-1] = 0); stage x[0] -> XT[0] ----
  for (int i = tid; i < 8320; i += NTHR) ((uint32_t*)(smc + SBUF0))[i] = 0u;
  {
    const float4* xr = (const float4*)x + (size_t)b0*32;
    for (int i = tid; i < 512; i += NTHR) {
      int row = i >> 5, c4 = i & 31;
      float4 vv = __ldcg(xr + row*32 + c4);
      *(uint2*)(smc + XT_B + row*272 + c4*8) = make_uint2(pk2(vv.x, vv.y), pk2(vv.z, vv.w));
    }
  }
  __syncthreads();

  // per-lane ldmatrix offset within an s buffer
  const uint32_t aOff = (uint32_t)(lane & 15)*1040 + (uint32_t)((lane >> 4) & 1)*16;
  const uint32_t aX0 = smb + XT_B + (uint32_t)(lane & 15)*272
                     + (uint32_t)((lane >> 4) & 1)*16;
  const char* winp = smc + WIN_B + (size_t)(w*8*32 + lane)*8;

  // update mapping (warps 0-7)
  const int r  = lane >> 2;
  const int hh = h0 + w*8 + (lane & 3)*2;
  float2 bin = make_float2(0.f, 0.f);
  if (w < 8) bin = *(const float2*)(b_in + hh);

  // readout mapping (warps 8-9 write out)
  const int oc = ((w - 8) & 1)*8 + (lane & 3)*2;
  float2 bo2 = make_float2(0.f, 0.f);
  if (w >= 8 && w < 10) bo2 = make_float2(__ldg(b_out + o0 + oc),
                                          __ldg(b_out + o0 + oc + 1));

  float v[4]  = {0.f,0.f,0.f,0.f};
  float a0s[4] = {0.f,0.f,0.f,0.f};
  float a1s[4] = {0.f,0.f,0.f,0.f};
  float sp[4] = {0.f,0.f,0.f,0.f};

  for (int t = 0; t <= T_STEPS; ++t) {
    const uint32_t sbase = smb + ((t & 1) ? SBUF1 : SBUF0);
    const uint32_t aH = sbase + aOff;
    const uint32_t aL = aH + SLO_OFF;

    if (w < 8) {
      if (t < T_STEPS) {
        // ---- update GEMM: W_rec @ s_hi (4 chains) + W_in @ x[t] (1 chain) ----
        float dA[4] = {0.f,0.f,0.f,0.f}, dB[4] = {0.f,0.f,0.f,0.f};
        float dC[4] = {0.f,0.f,0.f,0.f}, dD[4] = {0.f,0.f,0.f,0.f};
        float dX[4] = {0.f,0.f,0.f,0.f};
        #pragma unroll
        for (int ks = 0; ks < 32; ks += 4) {
          uint32_t f0, f1, f2, f3;
          LDSM4(f0, f1, f2, f3, aH + (uint32_t)ks*32);
          MMA16816(dA, f0, f1, f2, f3, bf0[ks], bf1[ks]);
          uint32_t g0, g1, g2, g3;
          LDSM4(g0, g1, g2, g3, aH + (uint32_t)(ks + 1)*32);
          MMA16816(dB, g0, g1, g2, g3, bf0[ks + 1], bf1[ks + 1]);
          uint32_t h0r, h1r, h2r, h3r;
          LDSM4(h0r, h1r, h2r, h3r, aH + (uint32_t)(ks + 2)*32);
          MMA16816(dC, h0r, h1r, h2r, h3r, bf0[ks + 2], bf1[ks + 2]);
          uint32_t i0, i1, i2, i3;
          LDSM4(i0, i1, i2, i3, aH + (uint32_t)(ks + 3)*32);
          MMA16816(dD, i0, i1, i2, i3, bf0[ks + 3], bf1[ks + 3]);
        }
        {
          const uint32_t aX = aX0 + (uint32_t)(t & 1)*4352;
          #pragma unroll
          for (int ks = 0; ks < 8; ++ks) {
            uint2 wf = *(const uint2*)(winp + ks*256);
            uint32_t f0, f1, f2, f3;
            LDSM4(f0, f1, f2, f3, aX + (uint32_t)ks*32);
            MMA16816(dX, f0, f1, f2, f3, wf.x, wf.y);
          }
        }
        // ---- GLIFR update ----
        float bv[4] = {bin.x, bin.y, bin.x, bin.y};
        #pragma unroll
        for (int j = 0; j < 4; ++j) {
          float y  = 0.5f*(dA[j] + dB[j] + dC[j] + dD[j] + dX[j] + bv[j]);
          a0s[j] = fmaf(a0s[j],  0.85f, -0.05f*sp[j]);
          a1s[j] = fmaf(a1s[j], -0.5f,  -0.05f*sp[j]);
          float it = y + a0s[j] + a1s[j] + 700.0f;
          v[j]  = v[j]*0.99f*(1.0f - 0.05f*sp[j]) + 0.00101953125f*it;
          sp[j] = 20.0f / (1.0f + __expf(-v[j]*0.02f));
        }
        // publish bf16 hi/lo
        const int slot = t & 1;
        float h0f = __bfloat162float(__float2bfloat16_rn(sp[0]));
        float h1f = __bfloat162float(__float2bfloat16_rn(sp[1]));
        float h2f = __bfloat162float(__float2bfloat16_rn(sp[2]));
        float h3f = __bfloat162float(__float2bfloat16_rn(sp[3]));
        __stcg(&g_rh[slot][b0 + r][hh >> 1],     pk2(sp[0], sp[1]));
        __stcg(&g_rh[slot][b0 + r + 8][hh >> 1], pk2(sp[2], sp[3]));
        __stcg(&g_rl[slot][b0 + r][hh >> 1],     pk2(sp[0] - h0f, sp[1] - h1f));
        __stcg(&g_rl[slot][b0 + r + 8][hh >> 1], pk2(sp[2] - h2f, sp[3] - h3f));

        // ---- update-warps-only barrier, then one thread raises our flag ----
        asm volatile("bar.sync 1, 256;" ::: "memory");
        if (tid == 0) {
          asm volatile("fence.acq_rel.gpu;" ::: "memory");   // release
          __stcg(&g_flag[btile][htile], (unsigned)(t + 1));
        }
      }
    } else if (w < 10) {
      // ---- readout hi GEMM: W_out_hi @ (s_hi + s_lo), 4 chains ----
      float dh0[4] = {0.f,0.f,0.f,0.f}, dh1[4] = {0.f,0.f,0.f,0.f};
      float dl0[4] = {0.f,0.f,0.f,0.f}, dl1[4] = {0.f,0.f,0.f,0.f};
      #pragma unroll
      for (int ks = 0; ks < 32; ks += 2) {
        uint32_t f0, f1, f2, f3;
        LDSM4(f0, f1, f2, f3, aH + (uint32_t)ks*32);
        MMA16816(dh0, f0, f1, f2, f3, bf0[ks], bf1[ks]);
        uint32_t g0, g1, g2, g3;
        LDSM4(g0, g1, g2, g3, aH + (uint32_t)(ks + 1)*32);
        MMA16816(dh1, g0, g1, g2, g3, bf0[ks + 1], bf1[ks + 1]);
        uint32_t h0r, h1r, h2r, h3r;
        LDSM4(h0r, h1r, h2r, h3r, aL + (uint32_t)ks*32);
        MMA16816(dl0, h0r, h1r, h2r, h3r, bf0[ks], bf1[ks]);
        uint32_t i0, i1, i2, i3;
        LDSM4(i0, i1, i2, i3, aL + (uint32_t)(ks + 1)*32);
        MMA16816(dl1, i0, i1, i2, i3, bf0[ks + 1], bf1[ks + 1]);
      }
      float d0 = dh0[0] + dh1[0] + dl0[0] + dl1[0];
      float d1 = dh0[1] + dh1[1] + dl0[1] + dl1[1];
      float d2 = dh0[2] + dh1[2] + dl0[2] + dl1[2];
      float d3 = dh0[3] + dh1[3] + dl0[3] + dl1[3];
      asm volatile("bar.sync 8, 128;" ::: "memory");
      if (t >= 1) {
        float* op = out + (size_t)(t - 1)*BATCH*NOUT + (size_t)(b0 + r)*NOUT + o0 + oc;
        *(float2*)op = make_float2(d0 + olo[r*18 + oc] + bo2.x,
                                   d1 + olo[r*18 + oc + 1] + bo2.y);
        float* op2 = op + 8*NOUT;
        *(float2*)op2 = make_float2(d2 + olo[(r + 8)*18 + oc] + bo2.x,
                                    d3 + olo[(r + 8)*18 + oc + 1] + bo2.y);
      }
    } else {
      // ---- readout lo GEMM: W_out_lo @ s_hi, 4 chains ----
      float dA[4] = {0.f,0.f,0.f,0.f}, dB[4] = {0.f,0.f,0.f,0.f};
      float dC[4] = {0.f,0.f,0.f,0.f}, dD[4] = {0.f,0.f,0.f,0.f};
      #pragma unroll
      for (int ks = 0; ks < 32; ks += 4) {
        uint32_t f0, f1, f2, f3;
        LDSM4(f0, f1, f2, f3, aH + (uint32_t)ks*32);
        MMA16816(dA, f0, f1, f2, f3, bf0[ks], bf1[ks]);
        uint32_t g0, g1, g2, g3;
        LDSM4(g0, g1, g2, g3, aH + (uint32_t)(ks + 1)*32);
        MMA16816(dB, g0, g1, g2, g3, bf0[ks + 1], bf1[ks + 1]);
        uint32_t h0r, h1r, h2r, h3r;
        LDSM4(h0r, h1r, h2r, h3r, aH + (uint32_t)(ks + 2)*32);
        MMA16816(dC, h0r, h1r, h2r, h3r, bf0[ks + 2], bf1[ks + 2]);
        uint32_t i0, i1, i2, i3;
        LDSM4(i0, i1, i2, i3, aH + (uint32_t)(ks + 3)*32);
        MMA16816(dD, i0, i1, i2, i3, bf0[ks + 3], bf1[ks + 3]);
      }
      int c = (w - 10)*8 + (lane & 3)*2;
      olo[r*18 + c]           = dA[0] + dB[0] + dC[0] + dD[0];
      olo[r*18 + c + 1]       = dA[1] + dB[1] + dC[1] + dD[1];
      olo[(r + 8)*18 + c]     = dA[2] + dB[2] + dC[2] + dD[2];
      olo[(r + 8)*18 + c + 1] = dA[3] + dB[3] + dC[3] + dD[3];
      asm volatile("bar.sync 8, 128;" ::: "memory");
    }

    if (t == T_STEPS) break;

    // ---- readout warps stage x[t+1] (update warps skip straight to poll) ----
    if (w >= 8) {
      int tn = (t + 1 < T_STEPS) ? t + 1 : (T_STEPS - 1);
      const float4* xr = (const float4*)(x + (size_t)tn*BATCH*NIN) + (size_t)b0*32;
      char* dst = smc + XT_B + ((t + 1) & 1)*4352;
      int i = (w - 8)*128 + lane;         // 128 threads cover 512 in 4 rounds
      #pragma unroll
      for (int jj = 0; jj < 4; ++jj, i += 128) {
        int row = i >> 5, c4 = i & 31;
        float4 vv = __ldcg(xr + row*32 + c4);
        *(uint2*)(dst + row*272 + c4*8) = make_uint2(pk2(vv.x, vv.y), pk2(vv.z, vv.w));
      }
    }

    // ---- per-warp acquire-correct flag poll ----
    poll_flags(&g_flag[btile][0], (unsigned)(t + 1));

    // ---- restage: bf16 rings -> sbuf[(t+1)&1] (pure copy, per-warp slices) ----
    {
      const int slot = t & 1;
      char* db = smc + (((t + 1) & 1) ? SBUF1 : SBUF0);
      #pragma unroll
      for (int j = 0; j < 6; ++j) {
        int i = j*NTHR + tid;             // 0..2303, valid < 2048
        if (i < 2048) {
          int half = i >> 10;             // 0 = hi, 1 = lo
          int ii = i & 1023;
          int b = ii >> 6, h8 = ii & 63;
          const unsigned* src = half ? &g_rl[slot][b0 + b][h8*4]
                                     : &g_rh[slot][b0 + b][h8*4];
          uint4 vv = __ldcg((const uint4*)src);
          *(uint4*)(db + half*SLO_OFF + b*1040 + h8*16) = vv;
        }
      }
    }
    __syncthreads();
  }

  // ---- closing barrier + flag reset (replay determinism) ----
  __syncthreads();
  if (tid == 0) {
    unsigned my = *((volatile unsigned*)&g_bgen[btile*32]);
    if (atomicAdd(&g_bcnt[btile*32], 1u) == 7u) {
      atomicExch(&g_bcnt[btile*32], 0u);
      atomicExch(&g_bgen[btile*32], my + 1u);
    }
    while (*((volatile unsigned*)&g_bgen[btile*32]) == my) { }
    __stcg(&g_flag[btile][htile], 0u);
  }
}

extern "C" void kernel_launch(void* const* d_in, const int* in_sizes, int n_in,
                              void* d_out, int out_size) {
  const float* x     = (const float*)d_in[0];
  const float* W_in  = (const float*)d_in[1];
  const float* b_in  = (const float*)d_in[2];
  const float* W_rec = (const float*)d_in[3];
  const float* W_out = (const float*)d_in[4];
  const float* b_out = (const float*)d_in[5];
  float* out = (float*)d_out;

  cudaFuncSetAttribute(bnn_kernel,
                       cudaFuncAttributeMaxDynamicSharedMemorySize, SMEM_BYTES);
  bnn_kernel<<<NBLK, NTHR, SMEM_BYTES>>>(x, W_in, b_in, W_rec, W_out, b_out, out);
}